// round 12
// baseline (speedup 1.0000x reference)
#include <cuda_runtime.h>
#include <cuda_fp16.h>
#include <cstdint>

// ---------------- problem constants ----------------
#define DIMC   512
#define NHEADS 16
#define SSZ    4
#define BWIN   2048          // 32 batches * 64 windows
#define MROWS  131072        // BWIN * 64 == B*L
#define CHID   2048          // mlp hidden

// ---------------- scratch (device globals; no allocs allowed) ----------------
// g_XN1: LN1 output (window order) until QKV GEMM; then reused as x1 residual
// buffer (image order, fp16) written by OP1.
// g_H1 head (MROWS*DIMC halves): fp16 copy of x (image order) from LN1 until
// OP1 consumes it; overwritten by OP2 afterwards.
__device__ __half g_XN1[(size_t)MROWS * DIMC];
__device__ __half g_QKV[(size_t)MROWS * 3 * DIMC];
__device__ __half g_O  [(size_t)MROWS * DIMC];
__device__ __half g_XN2[(size_t)MROWS * DIMC];
__device__ __half g_H1 [(size_t)MROWS * CHID];
__device__ __half g_Wq [3 * DIMC * DIMC];
__device__ __half g_Wp [DIMC * DIMC];
__device__ __half g_W1 [CHID * DIMC];
__device__ __half g_W2 [DIMC * CHID];
__device__ __half g_BM [64 * NHEADS * 64 * 64];   // bias+mask table, 8MB

#define NWQ (3 * DIMC * DIMC)
#define NWP (DIMC * DIMC)
#define NW1 (CHID * DIMC)
#define NW2 (DIMC * CHID)
#define NBM (64 * NHEADS * 64 * 64)

// ---------------- helpers ----------------
__device__ __forceinline__ float gelu_f(float x) {
    return 0.5f * x * (1.0f + erff(x * 0.7071067811865475f));
}

__device__ __forceinline__ uint32_t smem_u32(const void* p) {
    return (uint32_t)__cvta_generic_to_shared(p);
}

// token index in window order -> token index in (B,H,W) order (shift mapping)
__device__ __forceinline__ size_t win_to_img(int t) {
    int b_   = t >> 6, nn = t & 63;
    int bimg = b_ >> 6, widx = b_ & 63;
    int gh = ((widx >> 3) << 3) + (nn >> 3);
    int gw = ((widx & 7) << 3) + (nn & 7);
    int sh = (gh + SSZ) & 63;
    int sw = (gw + SSZ) & 63;
    return ((size_t)bimg << 12) + (size_t)(sh << 6) + (size_t)sw;
}

#define LDSM_X4(r0, r1, r2, r3, addr)                                          \
    asm volatile("ldmatrix.sync.aligned.m8n8.x4.shared.b16 {%0,%1,%2,%3}, [%4];" \
                 : "=r"(r0), "=r"(r1), "=r"(r2), "=r"(r3) : "r"(addr))

#define LDSM_X4_T(r0, r1, r2, r3, addr)                                        \
    asm volatile("ldmatrix.sync.aligned.m8n8.x4.trans.shared.b16 {%0,%1,%2,%3}, [%4];" \
                 : "=r"(r0), "=r"(r1), "=r"(r2), "=r"(r3) : "r"(addr))

#define MMA16816(d, a, b0, b1)                                                 \
    asm volatile(                                                              \
        "mma.sync.aligned.m16n8k16.row.col.f32.f16.f16.f32 "                   \
        "{%0,%1,%2,%3},{%4,%5,%6,%7},{%8,%9},{%0,%1,%2,%3};"                   \
        : "+f"((d)[0]), "+f"((d)[1]), "+f"((d)[2]), "+f"((d)[3])               \
        : "r"((a)[0]), "r"((a)[1]), "r"((a)[2]), "r"((a)[3]),                  \
          "r"(b0), "r"(b1))

__device__ __forceinline__ uint32_t h2bits(float x, float y) {
    __half2 h = __floats2half2_rn(x, y);
    return *(uint32_t*)&h;
}

// ---------------- weight convert (fp32 -> fp16) ----------------
__global__ void cvt_all(const float* __restrict__ wq, const float* __restrict__ wp,
                        const float* __restrict__ w1, const float* __restrict__ w2) {
    int i = blockIdx.x * 256 + threadIdx.x;
    if (i < NWQ) g_Wq[i] = __float2half(wq[i]);
    if (i < NWP) g_Wp[i] = __float2half(wp[i]);
    if (i < NW1) g_W1[i] = __float2half(w1[i]);
    if (i < NW2) g_W2[i] = __float2half(w2[i]);
}

// ---------------- bias+mask table: [widx][head][r][c] fp16 ----------------
__global__ void biasmask_k(const float* __restrict__ rpb) {
    int i = blockIdx.x * 256 + threadIdx.x;
    if (i >= NBM) return;
    int c    = i & 63;
    int r    = (i >> 6) & 63;
    int h    = (i >> 12) & 15;
    int widx = i >> 16;
    int rh = r >> 3, rw = r & 7;
    int mh = c >> 3, mw = c & 7;
    float bias = rpb[((rh - mh + 7) * 15 + (rw - mw + 7)) * NHEADS + h];
    int gh0 = ((widx >> 3) << 3) + rh, gw0 = ((widx & 7) << 3) + rw;
    int gh1 = ((widx >> 3) << 3) + mh, gw1 = ((widx & 7) << 3) + mw;
    int z0 = (gh0 < 56 ? 0 : (gh0 < 60 ? 1 : 2)) * 3 + (gw0 < 56 ? 0 : (gw0 < 60 ? 1 : 2));
    int z1 = (gh1 < 56 ? 0 : (gh1 < 60 ? 1 : 2)) * 3 + (gw1 < 56 ? 0 : (gw1 < 60 ? 1 : 2));
    g_BM[i] = __float2half(bias + (z0 == z1 ? 0.f : -100.f));
}

// ---------------- LN1 (fp32 input, shift+window remap) + fp16 x copy --------
__global__ void __launch_bounds__(256) ln1_kernel(const float* __restrict__ xin,
                                                  const float* __restrict__ gamma,
                                                  const float* __restrict__ beta) {
    int t    = (blockIdx.x * 256 + threadIdx.x) >> 5;
    int lane = threadIdx.x & 31;

    size_t src = win_to_img(t);
    const float* row = xin + src * DIMC;

    float4 v[4];
    float sum = 0.f, sq = 0.f;
#pragma unroll
    for (int p = 0; p < 4; p++) {
        v[p] = *(const float4*)(row + p * 128 + lane * 4);
        sum += v[p].x + v[p].y + v[p].z + v[p].w;
        sq  += v[p].x * v[p].x + v[p].y * v[p].y + v[p].z * v[p].z + v[p].w * v[p].w;
    }
#pragma unroll
    for (int o = 16; o > 0; o >>= 1) {
        sum += __shfl_xor_sync(0xffffffffu, sum, o);
        sq  += __shfl_xor_sync(0xffffffffu, sq, o);
    }
    float mu   = sum * (1.f / 512.f);
    float var  = sq * (1.f / 512.f) - mu * mu;
    float rstd = rsqrtf(var + 1e-5f);

    __half* orow = g_XN1 + (size_t)t * DIMC;
    __half* xrow = g_H1 + src * DIMC;      // fp16 x copy (image order)
#pragma unroll
    for (int p = 0; p < 4; p++) {
        int c = p * 128 + lane * 4;
        float4 g4 = *(const float4*)(gamma + c);
        float4 b4 = *(const float4*)(beta + c);
        __half2 h0 = __floats2half2_rn((v[p].x - mu) * rstd * g4.x + b4.x,
                                       (v[p].y - mu) * rstd * g4.y + b4.y);
        __half2 h1 = __floats2half2_rn((v[p].z - mu) * rstd * g4.z + b4.z,
                                       (v[p].w - mu) * rstd * g4.w + b4.w);
        uint2 u;
        u.x = *(uint32_t*)&h0;
        u.y = *(uint32_t*)&h1;
        *(uint2*)(orow + c) = u;
        __half2 x0 = __floats2half2_rn(v[p].x, v[p].y);
        __half2 x1 = __floats2half2_rn(v[p].z, v[p].w);
        uint2 ux;
        ux.x = *(uint32_t*)&x0;
        ux.y = *(uint32_t*)&x1;
        *(uint2*)(xrow + c) = ux;
    }
}

// ---------------- LN2 (fp16 x1 input from g_XN1, image order) ---------------
__global__ void __launch_bounds__(256) ln2_kernel(const float* __restrict__ gamma,
                                                  const float* __restrict__ beta) {
    int t    = (blockIdx.x * 256 + threadIdx.x) >> 5;
    int lane = threadIdx.x & 31;

    const __half* row = g_XN1 + (size_t)t * DIMC;

    float v[16];
    float sum = 0.f, sq = 0.f;
#pragma unroll
    for (int p = 0; p < 4; p++) {
        uint2 u = *(const uint2*)(row + p * 128 + lane * 4);
        const __half2* hp = (const __half2*)&u;
        float2 f0 = __half22float2(hp[0]);
        float2 f1 = __half22float2(hp[1]);
        v[p * 4]     = f0.x; v[p * 4 + 1] = f0.y;
        v[p * 4 + 2] = f1.x; v[p * 4 + 3] = f1.y;
        sum += f0.x + f0.y + f1.x + f1.y;
        sq  += f0.x * f0.x + f0.y * f0.y + f1.x * f1.x + f1.y * f1.y;
    }
#pragma unroll
    for (int o = 16; o > 0; o >>= 1) {
        sum += __shfl_xor_sync(0xffffffffu, sum, o);
        sq  += __shfl_xor_sync(0xffffffffu, sq, o);
    }
    float mu   = sum * (1.f / 512.f);
    float var  = sq * (1.f / 512.f) - mu * mu;
    float rstd = rsqrtf(var + 1e-5f);

    __half* orow = g_XN2 + (size_t)t * DIMC;
#pragma unroll
    for (int p = 0; p < 4; p++) {
        int c = p * 128 + lane * 4;
        float4 g4 = *(const float4*)(gamma + c);
        float4 b4 = *(const float4*)(beta + c);
        __half2 h0 = __floats2half2_rn((v[p * 4]     - mu) * rstd * g4.x + b4.x,
                                       (v[p * 4 + 1] - mu) * rstd * g4.y + b4.y);
        __half2 h1 = __floats2half2_rn((v[p * 4 + 2] - mu) * rstd * g4.z + b4.z,
                                       (v[p * 4 + 3] - mu) * rstd * g4.w + b4.w);
        uint2 u;
        u.x = *(uint32_t*)&h0;
        u.y = *(uint32_t*)&h1;
        *(uint2*)(orow + c) = u;
    }
}

// ---------------- fp16 mma.sync GEMM: C[M,N] = A[M,K] @ W[N,K]^T ------------
// BM=128, BN=128, BK=64, 3-stage cp.async, XOR-8 swizzle, 8 warps of 64x32.
// OP 0: -> g_QKV(f16) = acc + bias                      (smem-staged)
// OP 1: -> g_XN1[remap](f16) = x16[remap] + acc + bias  (x1 residual, fp16)
// OP 2: -> g_H1(f16) = gelu(acc + bias)                 (smem-staged)
// OP 3: -> out(f32, write-only) = x1(f16) + acc + bias
template <int NTOT, int KTOT, int OP>
__global__ void __launch_bounds__(256, 2) gemm_f16(const float* __restrict__ bias,
                                                   float* __restrict__ outp) {
    constexpr int BM = 128, BN = 128, BK = 64, STAGES = 3;
    constexpr int KT = KTOT / BK;
    constexpr uint32_t AB    = BM * BK * 2;   // 16KB
    constexpr uint32_t BB    = BN * BK * 2;   // 16KB
    constexpr uint32_t STAGE = AB + BB;       // 32KB

    extern __shared__ char smem[];
    const uint32_t sbase = smem_u32(smem);
    const int tid = threadIdx.x;

    const __half* A;
    const __half* Bw;
    if (OP == 0)      { A = g_XN1; Bw = g_Wq; }
    else if (OP == 1) { A = g_O;   Bw = g_Wp; }
    else if (OP == 2) { A = g_XN2; Bw = g_W1; }
    else              { A = g_H1;  Bw = g_W2; }

    const int m0 = blockIdx.y * BM;
    const int n0 = blockIdx.x * BN;

    auto load_tile = [&](int kt, int s) {
        const __half* gA = A + (size_t)m0 * KTOT + kt * BK;
        const __half* gB = Bw + (size_t)n0 * KTOT + kt * BK;
#pragma unroll
        for (int i = 0; i < 4; i++) {
            int idx = i * 256 + tid;
            int r = idx >> 3, g = idx & 7;
            uint32_t off = (uint32_t)(r * 128 + ((g ^ (r & 7)) << 4));
            uint32_t da = sbase + (uint32_t)s * STAGE + off;
            const __half* pa = gA + (size_t)r * KTOT + g * 8;
            asm volatile("cp.async.cg.shared.global [%0], [%1], 16;\n" ::"r"(da), "l"(pa));
            uint32_t db = sbase + (uint32_t)s * STAGE + AB + off;
            const __half* pb = gB + (size_t)r * KTOT + g * 8;
            asm volatile("cp.async.cg.shared.global [%0], [%1], 16;\n" ::"r"(db), "l"(pb));
        }
        asm volatile("cp.async.commit_group;\n");
    };

    const int w    = tid >> 5;
    const int wm   = w >> 2;
    const int wn   = w & 3;
    const int lane = tid & 31;
    const int grp  = lane >> 2;
    const int tig  = lane & 3;

    float acc[4][4][4];
#pragma unroll
    for (int i = 0; i < 4; i++)
#pragma unroll
        for (int j = 0; j < 4; j++)
#pragma unroll
            for (int r = 0; r < 4; r++) acc[i][j][r] = 0.f;

    const int a_row  = wm * 64 + (lane & 15);
    const int a_chk0 = lane >> 4;
    const int b_row  = wn * 32 + (lane & 7) + ((lane >> 4) << 3);
    const int b_chk0 = (lane >> 3) & 1;

    load_tile(0, 0);
    load_tile(1, 1);

#pragma unroll 1
    for (int kt = 0; kt < KT; ++kt) {
        if (kt + 2 < KT) asm volatile("cp.async.wait_group 1;\n");
        else             asm volatile("cp.async.wait_group 0;\n");
        __syncthreads();

        if (kt + 2 < KT) load_tile(kt + 2, (kt + 2) % STAGES);

        const uint32_t stA = sbase + (uint32_t)(kt % STAGES) * STAGE;
        const uint32_t stB = stA + AB;

#pragma unroll
        for (int ks = 0; ks < 4; ++ks) {
            uint32_t a[4][4], b[2][4];
#pragma unroll
            for (int mt = 0; mt < 4; ++mt) {
                int r = a_row + mt * 16;
                int c = ks * 2 + a_chk0;
                uint32_t ad = stA + (uint32_t)(r * 128 + ((c ^ (r & 7)) << 4));
                LDSM_X4(a[mt][0], a[mt][1], a[mt][2], a[mt][3], ad);
            }
#pragma unroll
            for (int nt2 = 0; nt2 < 2; ++nt2) {
                int r = b_row + nt2 * 16;
                int c = ks * 2 + b_chk0;
                uint32_t bd = stB + (uint32_t)(r * 128 + ((c ^ (r & 7)) << 4));
                LDSM_X4(b[nt2][0], b[nt2][1], b[nt2][2], b[nt2][3], bd);
            }
#pragma unroll
            for (int mt = 0; mt < 4; ++mt)
#pragma unroll
                for (int nt = 0; nt < 4; ++nt)
                    MMA16816(acc[mt][nt], a[mt], b[nt >> 1][(nt & 1) * 2], b[nt >> 1][(nt & 1) * 2 + 1]);
        }
    }

    // ---- epilogue ----
    if (OP == 0 || OP == 2) {
        constexpr int OSTR = 136;
        __half* sOut = (__half*)smem;
        __syncthreads();
#pragma unroll
        for (int mt = 0; mt < 4; ++mt) {
            int row_lo = wm * 64 + mt * 16 + grp;
#pragma unroll
            for (int nt = 0; nt < 4; ++nt) {
                int col = wn * 32 + nt * 8 + 2 * tig;
                float b0 = bias[n0 + col], b1 = bias[n0 + col + 1];
                float v00 = acc[mt][nt][0] + b0;
                float v01 = acc[mt][nt][1] + b1;
                float v10 = acc[mt][nt][2] + b0;
                float v11 = acc[mt][nt][3] + b1;
                if (OP == 2) {
                    v00 = gelu_f(v00); v01 = gelu_f(v01);
                    v10 = gelu_f(v10); v11 = gelu_f(v11);
                }
                *(__half2*)(sOut + row_lo * OSTR + col)       = __floats2half2_rn(v00, v01);
                *(__half2*)(sOut + (row_lo + 8) * OSTR + col) = __floats2half2_rn(v10, v11);
            }
        }
        __syncthreads();
        __half* dst = (OP == 0) ? g_QKV : g_H1;
#pragma unroll
        for (int i = 0; i < 8; i++) {
            int id  = i * 256 + tid;
            int row = id >> 4, c16 = id & 15;
            uint4 v = *(const uint4*)(sOut + row * OSTR + c16 * 8);
            *(uint4*)(dst + (size_t)(m0 + row) * NTOT + n0 + c16 * 8) = v;
        }
    } else {
#pragma unroll
        for (int mt = 0; mt < 4; ++mt) {
            int r_lo = m0 + wm * 64 + mt * 16 + grp;
            int r_hi = r_lo + 8;
            size_t d_lo = 0, d_hi = 0;
            if (OP == 1) {
                d_lo = win_to_img(r_lo) * DIMC;
                d_hi = win_to_img(r_hi) * DIMC;
            }
#pragma unroll
            for (int nt = 0; nt < 4; ++nt) {
                int c0 = n0 + wn * 32 + nt * 8 + 2 * tig;
                float b0 = bias[c0], b1 = bias[c0 + 1];
                float v00 = acc[mt][nt][0] + b0;
                float v01 = acc[mt][nt][1] + b1;
                float v10 = acc[mt][nt][2] + b0;
                float v11 = acc[mt][nt][3] + b1;
                if (OP == 1) {
                    // x1 = fp16(x)[remap] + proj_out -> fp16 residual buffer
                    float2 a0 = __half22float2(*(const __half2*)(g_H1 + d_lo + c0));
                    float2 a1 = __half22float2(*(const __half2*)(g_H1 + d_hi + c0));
                    *(__half2*)(g_XN1 + d_lo + c0) = __floats2half2_rn(a0.x + v00, a0.y + v01);
                    *(__half2*)(g_XN1 + d_hi + c0) = __floats2half2_rn(a1.x + v10, a1.y + v11);
                } else {
                    // final out = x1 + fc2_out  (write-only fp32)
                    size_t o0 = (size_t)r_lo * NTOT + c0;
                    size_t o1 = (size_t)r_hi * NTOT + c0;
                    float2 x0  = __half22float2(*(const __half2*)(g_XN1 + o0));
                    float2 x1v = __half22float2(*(const __half2*)(g_XN1 + o1));
                    *(float2*)(outp + o0) = make_float2(x0.x + v00, x0.y + v01);
                    *(float2*)(outp + o1) = make_float2(x1v.x + v10, x1v.y + v11);
                }
            }
        }
    }
}

// ---------------- attention via mma.sync: one 128-thread block per (win,head)
__global__ void __launch_bounds__(128) attn_kernel() {
    __shared__ __align__(16) __half sQ[64 * 32];
    __shared__ __align__(16) __half sK[64 * 32];
    __shared__ __align__(16) __half sV[64 * 32];

    const int bh   = blockIdx.x;
    const int b_   = bh >> 4;
    const int h    = bh & 15;
    const int tid  = threadIdx.x;
    const int w    = tid >> 5;
    const int lane = tid & 31;
    const int grp  = lane >> 2;
    const int tig  = lane & 3;

    const uint32_t qb = smem_u32(sQ);
    const uint32_t kb = smem_u32(sK);
    const uint32_t vb = smem_u32(sV);

    auto qk_off = [](int r, int g) -> uint32_t {
        return (uint32_t)((r >> 1) * 128 + (((((r & 1) << 2) | g) ^ ((r >> 1) & 7)) << 4));
    };

    const __half* base = g_QKV + (size_t)(b_ * 64) * (3 * DIMC) + h * 32;
#pragma unroll
    for (int i = 0; i < 2; i++) {
        int idx = i * 128 + tid;
        int r = idx >> 2, g = idx & 3;
        const __half* rowp = base + (size_t)r * (3 * DIMC);
        uint32_t off = qk_off(r, g);
        *(uint4*)((char*)sQ + off) = *(const uint4*)(rowp + g * 8);
        *(uint4*)((char*)sK + off) = *(const uint4*)(rowp + DIMC + g * 8);
        *(uint4*)((char*)sV + off) = *(const uint4*)(rowp + 2 * DIMC + g * 8);
    }
    __syncthreads();

    float s[8][4];
#pragma unroll
    for (int i = 0; i < 8; i++)
#pragma unroll
        for (int j = 0; j < 4; j++) s[i][j] = 0.f;

    const int a_row  = w * 16 + (lane & 15);
    const int a_chk0 = lane >> 4;
    const int b_row  = (lane & 7) + ((lane >> 4) << 3);
    const int b_chk0 = (lane >> 3) & 1;

#pragma unroll
    for (int ks = 0; ks < 2; ++ks) {
        uint32_t a[4], b[4][4];
        LDSM_X4(a[0], a[1], a[2], a[3], qb + qk_off(a_row, ks * 2 + a_chk0));
#pragma unroll
        for (int nt2 = 0; nt2 < 4; ++nt2)
            LDSM_X4(b[nt2][0], b[nt2][1], b[nt2][2], b[nt2][3],
                    kb + qk_off(nt2 * 16 + b_row, ks * 2 + b_chk0));
#pragma unroll
        for (int nt = 0; nt < 8; ++nt)
            MMA16816(s[nt], a, b[nt >> 1][(nt & 1) * 2], b[nt >> 1][(nt & 1) * 2 + 1]);
    }

    // ---- bias+mask from precomputed table; exp; row sums ----
    const float scale = 0.17677669529663687f;
    const int r0 = w * 16 + grp;
    const int r1 = r0 + 8;
    const int widx = b_ & 63;
    const __half* T0 = g_BM + (((size_t)widx * NHEADS + h) * 64 + r0) * 64;
    const __half* T1 = g_BM + (((size_t)widx * NHEADS + h) * 64 + r1) * 64;

    float sum0 = 0.f, sum1 = 0.f;
#pragma unroll
    for (int nt = 0; nt < 8; ++nt) {
        int c = nt * 8 + tig * 2;
        float2 t0 = __half22float2(*(const __half2*)(T0 + c));
        float2 t1 = __half22float2(*(const __half2*)(T1 + c));
        float e00 = __expf(s[nt][0] * scale + t0.x);
        float e01 = __expf(s[nt][1] * scale + t0.y);
        float e10 = __expf(s[nt][2] * scale + t1.x);
        float e11 = __expf(s[nt][3] * scale + t1.y);
        s[nt][0] = e00; s[nt][1] = e01;
        s[nt][2] = e10; s[nt][3] = e11;
        sum0 += e00 + e01;
        sum1 += e10 + e11;
    }
    sum0 += __shfl_xor_sync(0xffffffffu, sum0, 1);
    sum0 += __shfl_xor_sync(0xffffffffu, sum0, 2);
    sum1 += __shfl_xor_sync(0xffffffffu, sum1, 1);
    sum1 += __shfl_xor_sync(0xffffffffu, sum1, 2);

    float o[4][4];
#pragma unroll
    for (int i = 0; i < 4; i++)
#pragma unroll
        for (int j = 0; j < 4; j++) o[i][j] = 0.f;

#pragma unroll
    for (int ks2 = 0; ks2 < 4; ++ks2) {
        uint32_t pa[4];
        pa[0] = h2bits(s[ks2 * 2][0],     s[ks2 * 2][1]);
        pa[1] = h2bits(s[ks2 * 2][2],     s[ks2 * 2][3]);
        pa[2] = h2bits(s[ks2 * 2 + 1][0], s[ks2 * 2 + 1][1]);
        pa[3] = h2bits(s[ks2 * 2 + 1][2], s[ks2 * 2 + 1][3]);
        int vrow = ks2 * 16 + (lane & 15);
        uint32_t bv0[4], bv1[4];
        LDSM_X4_T(bv0[0], bv0[1], bv0[2], bv0[3], vb + qk_off(vrow, lane >> 4));
        LDSM_X4_T(bv1[0], bv1[1], bv1[2], bv1[3], vb + qk_off(vrow, 2 + (lane >> 4)));
        MMA16816(o[0], pa, bv0[0], bv0[1]);
        MMA16816(o[1], pa, bv0[2], bv0[3]);
        MMA16816(o[2], pa, bv1[0], bv1[1]);
        MMA16816(o[3], pa, bv1[2], bv1[3]);
    }

    const float inv0 = 1.f / sum0;
    const float inv1 = 1.f / sum1;
    __half* o0 = g_O + (size_t)(b_ * 64 + r0) * DIMC + h * 32;
    __half* o1 = g_O + (size_t)(b_ * 64 + r1) * DIMC + h * 32;
#pragma unroll
    for (int nt = 0; nt < 4; ++nt) {
        int d = nt * 8 + tig * 2;
        *(__half2*)(o0 + d) = __floats2half2_rn(o[nt][0] * inv0, o[nt][1] * inv0);
        *(__half2*)(o1 + d) = __floats2half2_rn(o[nt][2] * inv1, o[nt][3] * inv1);
    }
}

// ---------------- host launcher ----------------
extern "C" void kernel_launch(void* const* d_in, const int* in_sizes, int n_in,
                              void* d_out, int out_size) {
    const float* x      = (const float*)d_in[0];
    const float* n1g    = (const float*)d_in[1];
    const float* n1b    = (const float*)d_in[2];
    const float* qkv_w  = (const float*)d_in[3];
    const float* qkv_b  = (const float*)d_in[4];
    const float* proj_w = (const float*)d_in[5];
    const float* proj_b = (const float*)d_in[6];
    const float* rpb    = (const float*)d_in[7];
    const float* n2g    = (const float*)d_in[8];
    const float* n2b    = (const float*)d_in[9];
    const float* fc1_w  = (const float*)d_in[10];
    const float* fc1_b  = (const float*)d_in[11];
    const float* fc2_w  = (const float*)d_in[12];
    const float* fc2_b  = (const float*)d_in[13];
    float* out = (float*)d_out;

    constexpr int SMEMB = 3 * (128 * 64 * 2 + 128 * 64 * 2);  // 98304 bytes

    cudaFuncSetAttribute(gemm_f16<1536, 512, 0>, cudaFuncAttributeMaxDynamicSharedMemorySize, SMEMB);
    cudaFuncSetAttribute(gemm_f16<512,  512, 1>, cudaFuncAttributeMaxDynamicSharedMemorySize, SMEMB);
    cudaFuncSetAttribute(gemm_f16<2048, 512, 2>, cudaFuncAttributeMaxDynamicSharedMemorySize, SMEMB);
    cudaFuncSetAttribute(gemm_f16<512, 2048, 3>, cudaFuncAttributeMaxDynamicSharedMemorySize, SMEMB);

    // weights -> fp16 copies; bias+mask table
    cvt_all<<<(NW1 + 255) / 256, 256>>>(qkv_w, proj_w, fc1_w, fc2_w);
    biasmask_k<<<(NBM + 255) / 256, 256>>>(rpb);

    // LN1 + shift + window partition -> g_XN1; fp16 x copy -> g_H1 head
    ln1_kernel<<<MROWS / 8, 256>>>(x, n1g, n1b);

    // QKV projection
    gemm_f16<1536, 512, 0><<<dim3(1536 / 128, MROWS / 128), 256, SMEMB>>>(qkv_b, nullptr);

    // windowed attention (tensor-core, table bias+mask)
    attn_kernel<<<BWIN * NHEADS, 128>>>();

    // output projection + window reverse + shift + residual -> g_XN1 (x1, fp16)
    gemm_f16<512, 512, 1><<<dim3(512 / 128, MROWS / 128), 256, SMEMB>>>(proj_b, nullptr);

    // LN2 (reads fp16 x1)
    ln2_kernel<<<MROWS / 8, 256>>>(n2g, n2b);

    // FC1 + gelu (overwrites g_H1 — x copy dead by now)
    gemm_f16<2048, 512, 2><<<dim3(2048 / 128, MROWS / 128), 256, SMEMB>>>(fc1_b, nullptr);

    // FC2 + residual: out = x1 + acc + bias (write-only fp32)
    gemm_f16<512, 2048, 3><<<dim3(512 / 128, MROWS / 128), 256, SMEMB>>>(fc2_b, out);
}

// round 13
// speedup vs baseline: 1.0251x; 1.0251x over previous
#include <cuda_runtime.h>
#include <cuda_fp16.h>
#include <cstdint>

// ---------------- problem constants ----------------
#define DIMC   512
#define NHEADS 16
#define SSZ    4
#define BWIN   2048          // 32 batches * 64 windows
#define MROWS  131072        // BWIN * 64 == B*L
#define CHID   2048          // mlp hidden

// ---------------- scratch (device globals; no allocs allowed) ----------------
// g_XN1: LN1 output (window order) until QKV GEMM; then reused as x1 residual
// buffer (image order, fp16) written by OP1.
__device__ __half g_XN1[(size_t)MROWS * DIMC];
__device__ __half g_QKV[(size_t)MROWS * 3 * DIMC];
__device__ __half g_O  [(size_t)MROWS * DIMC];
__device__ __half g_XN2[(size_t)MROWS * DIMC];
__device__ __half g_H1 [(size_t)MROWS * CHID];
__device__ __half g_Wq [3 * DIMC * DIMC];
__device__ __half g_Wp [DIMC * DIMC];
__device__ __half g_W1 [CHID * DIMC];
__device__ __half g_W2 [DIMC * CHID];
__device__ float  g_RPBt[NHEADS * 225];   // transposed rel-pos bias

#define NWQ (3 * DIMC * DIMC)
#define NWP (DIMC * DIMC)
#define NW1 (CHID * DIMC)
#define NW2 (DIMC * CHID)

// ---------------- helpers ----------------
__device__ __forceinline__ float gelu_f(float x) {
    return 0.5f * x * (1.0f + erff(x * 0.7071067811865475f));
}

__device__ __forceinline__ uint32_t smem_u32(const void* p) {
    return (uint32_t)__cvta_generic_to_shared(p);
}

// token index in window order -> token index in (B,H,W) order (shift mapping)
__device__ __forceinline__ size_t win_to_img(int t) {
    int b_   = t >> 6, nn = t & 63;
    int bimg = b_ >> 6, widx = b_ & 63;
    int gh = ((widx >> 3) << 3) + (nn >> 3);
    int gw = ((widx & 7) << 3) + (nn & 7);
    int sh = (gh + SSZ) & 63;
    int sw = (gw + SSZ) & 63;
    return ((size_t)bimg << 12) + (size_t)(sh << 6) + (size_t)sw;
}

#define LDSM_X4(r0, r1, r2, r3, addr)                                          \
    asm volatile("ldmatrix.sync.aligned.m8n8.x4.shared.b16 {%0,%1,%2,%3}, [%4];" \
                 : "=r"(r0), "=r"(r1), "=r"(r2), "=r"(r3) : "r"(addr))

#define LDSM_X4_T(r0, r1, r2, r3, addr)                                        \
    asm volatile("ldmatrix.sync.aligned.m8n8.x4.trans.shared.b16 {%0,%1,%2,%3}, [%4];" \
                 : "=r"(r0), "=r"(r1), "=r"(r2), "=r"(r3) : "r"(addr))

#define MMA16816(d, a, b0, b1)                                                 \
    asm volatile(                                                              \
        "mma.sync.aligned.m16n8k16.row.col.f32.f16.f16.f32 "                   \
        "{%0,%1,%2,%3},{%4,%5,%6,%7},{%8,%9},{%0,%1,%2,%3};"                   \
        : "+f"((d)[0]), "+f"((d)[1]), "+f"((d)[2]), "+f"((d)[3])               \
        : "r"((a)[0]), "r"((a)[1]), "r"((a)[2]), "r"((a)[3]),                  \
          "r"(b0), "r"(b1))

__device__ __forceinline__ uint32_t h2bits(float x, float y) {
    __half2 h = __floats2half2_rn(x, y);
    return *(uint32_t*)&h;
}

// ---------------- weight convert + rpb transpose ----------------
__global__ void cvt_all(const float* __restrict__ wq, const float* __restrict__ wp,
                        const float* __restrict__ w1, const float* __restrict__ w2,
                        const float* __restrict__ rpb) {
    int i = blockIdx.x * 256 + threadIdx.x;
    if (i < NWQ) g_Wq[i] = __float2half(wq[i]);
    if (i < NWP) g_Wp[i] = __float2half(wp[i]);
    if (i < NW1) g_W1[i] = __float2half(w1[i]);
    if (i < NW2) g_W2[i] = __float2half(w2[i]);
    if (i < NHEADS * 225) {
        int h = i / 225, j = i % 225;
        g_RPBt[i] = rpb[j * NHEADS + h];
    }
}

// ---------------- LN1 (fp32 input, shift+window remap) ----------------
__global__ void __launch_bounds__(256) ln1_kernel(const float* __restrict__ xin,
                                                  const float* __restrict__ gamma,
                                                  const float* __restrict__ beta) {
    int t    = (blockIdx.x * 256 + threadIdx.x) >> 5;
    int lane = threadIdx.x & 31;

    size_t src = win_to_img(t);
    const float* row = xin + src * DIMC;

    float4 v[4];
    float sum = 0.f, sq = 0.f;
#pragma unroll
    for (int p = 0; p < 4; p++) {
        v[p] = *(const float4*)(row + p * 128 + lane * 4);
        sum += v[p].x + v[p].y + v[p].z + v[p].w;
        sq  += v[p].x * v[p].x + v[p].y * v[p].y + v[p].z * v[p].z + v[p].w * v[p].w;
    }
#pragma unroll
    for (int o = 16; o > 0; o >>= 1) {
        sum += __shfl_xor_sync(0xffffffffu, sum, o);
        sq  += __shfl_xor_sync(0xffffffffu, sq, o);
    }
    float mu   = sum * (1.f / 512.f);
    float var  = sq * (1.f / 512.f) - mu * mu;
    float rstd = rsqrtf(var + 1e-5f);

    __half* orow = g_XN1 + (size_t)t * DIMC;
#pragma unroll
    for (int p = 0; p < 4; p++) {
        int c = p * 128 + lane * 4;
        float4 g4 = *(const float4*)(gamma + c);
        float4 b4 = *(const float4*)(beta + c);
        __half2 h0 = __floats2half2_rn((v[p].x - mu) * rstd * g4.x + b4.x,
                                       (v[p].y - mu) * rstd * g4.y + b4.y);
        __half2 h1 = __floats2half2_rn((v[p].z - mu) * rstd * g4.z + b4.z,
                                       (v[p].w - mu) * rstd * g4.w + b4.w);
        uint2 u;
        u.x = *(uint32_t*)&h0;
        u.y = *(uint32_t*)&h1;
        *(uint2*)(orow + c) = u;
    }
}

// ---------------- LN2 (fp16 x1 input from g_XN1, image order) ---------------
__global__ void __launch_bounds__(256) ln2_kernel(const float* __restrict__ gamma,
                                                  const float* __restrict__ beta) {
    int t    = (blockIdx.x * 256 + threadIdx.x) >> 5;
    int lane = threadIdx.x & 31;

    const __half* row = g_XN1 + (size_t)t * DIMC;

    float v[16];
    float sum = 0.f, sq = 0.f;
#pragma unroll
    for (int p = 0; p < 4; p++) {
        uint2 u = *(const uint2*)(row + p * 128 + lane * 4);
        const __half2* hp = (const __half2*)&u;
        float2 f0 = __half22float2(hp[0]);
        float2 f1 = __half22float2(hp[1]);
        v[p * 4]     = f0.x; v[p * 4 + 1] = f0.y;
        v[p * 4 + 2] = f1.x; v[p * 4 + 3] = f1.y;
        sum += f0.x + f0.y + f1.x + f1.y;
        sq  += f0.x * f0.x + f0.y * f0.y + f1.x * f1.x + f1.y * f1.y;
    }
#pragma unroll
    for (int o = 16; o > 0; o >>= 1) {
        sum += __shfl_xor_sync(0xffffffffu, sum, o);
        sq  += __shfl_xor_sync(0xffffffffu, sq, o);
    }
    float mu   = sum * (1.f / 512.f);
    float var  = sq * (1.f / 512.f) - mu * mu;
    float rstd = rsqrtf(var + 1e-5f);

    __half* orow = g_XN2 + (size_t)t * DIMC;
#pragma unroll
    for (int p = 0; p < 4; p++) {
        int c = p * 128 + lane * 4;
        float4 g4 = *(const float4*)(gamma + c);
        float4 b4 = *(const float4*)(beta + c);
        __half2 h0 = __floats2half2_rn((v[p * 4]     - mu) * rstd * g4.x + b4.x,
                                       (v[p * 4 + 1] - mu) * rstd * g4.y + b4.y);
        __half2 h1 = __floats2half2_rn((v[p * 4 + 2] - mu) * rstd * g4.z + b4.z,
                                       (v[p * 4 + 3] - mu) * rstd * g4.w + b4.w);
        uint2 u;
        u.x = *(uint32_t*)&h0;
        u.y = *(uint32_t*)&h1;
        *(uint2*)(orow + c) = u;
    }
}

// ---------------- fp16 mma.sync GEMM: C[M,N] = A[M,K] @ W[N,K]^T ------------
// BM=128, BN=128, BK=64, 3-stage cp.async, XOR-8 swizzle, 8 warps of 64x32.
// ALL epilogues smem-staged for coalesced global traffic.
// OP 0: -> g_QKV(f16) = acc + bias
// OP 1: -> g_XN1[remap](f16) = x[remap](f32) + acc + bias   (x1 residual)
// OP 2: -> g_H1(f16) = gelu(acc + bias)
// OP 3: -> out(f32, write-only) = x1(f16) + acc + bias
template <int NTOT, int KTOT, int OP>
__global__ void __launch_bounds__(256, 2) gemm_f16(const float* __restrict__ bias,
                                                   const float* __restrict__ aux,
                                                   float* __restrict__ outp) {
    constexpr int BM = 128, BN = 128, BK = 64, STAGES = 3;
    constexpr int KT = KTOT / BK;
    constexpr uint32_t AB    = BM * BK * 2;   // 16KB
    constexpr uint32_t BB    = BN * BK * 2;   // 16KB
    constexpr uint32_t STAGE = AB + BB;       // 32KB

    extern __shared__ char smem[];
    const uint32_t sbase = smem_u32(smem);
    const int tid = threadIdx.x;

    const __half* A;
    const __half* Bw;
    if (OP == 0)      { A = g_XN1; Bw = g_Wq; }
    else if (OP == 1) { A = g_O;   Bw = g_Wp; }
    else if (OP == 2) { A = g_XN2; Bw = g_W1; }
    else              { A = g_H1;  Bw = g_W2; }

    const int m0 = blockIdx.y * BM;
    const int n0 = blockIdx.x * BN;

    auto load_tile = [&](int kt, int s) {
        const __half* gA = A + (size_t)m0 * KTOT + kt * BK;
        const __half* gB = Bw + (size_t)n0 * KTOT + kt * BK;
#pragma unroll
        for (int i = 0; i < 4; i++) {
            int idx = i * 256 + tid;
            int r = idx >> 3, g = idx & 7;
            uint32_t off = (uint32_t)(r * 128 + ((g ^ (r & 7)) << 4));
            uint32_t da = sbase + (uint32_t)s * STAGE + off;
            const __half* pa = gA + (size_t)r * KTOT + g * 8;
            asm volatile("cp.async.cg.shared.global [%0], [%1], 16;\n" ::"r"(da), "l"(pa));
            uint32_t db = sbase + (uint32_t)s * STAGE + AB + off;
            const __half* pb = gB + (size_t)r * KTOT + g * 8;
            asm volatile("cp.async.cg.shared.global [%0], [%1], 16;\n" ::"r"(db), "l"(pb));
        }
        asm volatile("cp.async.commit_group;\n");
    };

    const int w    = tid >> 5;
    const int wm   = w >> 2;
    const int wn   = w & 3;
    const int lane = tid & 31;
    const int grp  = lane >> 2;
    const int tig  = lane & 3;

    float acc[4][4][4];
#pragma unroll
    for (int i = 0; i < 4; i++)
#pragma unroll
        for (int j = 0; j < 4; j++)
#pragma unroll
            for (int r = 0; r < 4; r++) acc[i][j][r] = 0.f;

    const int a_row  = wm * 64 + (lane & 15);
    const int a_chk0 = lane >> 4;
    const int b_row  = wn * 32 + (lane & 7) + ((lane >> 4) << 3);
    const int b_chk0 = (lane >> 3) & 1;

    load_tile(0, 0);
    load_tile(1, 1);

#pragma unroll 1
    for (int kt = 0; kt < KT; ++kt) {
        if (kt + 2 < KT) asm volatile("cp.async.wait_group 1;\n");
        else             asm volatile("cp.async.wait_group 0;\n");
        __syncthreads();

        if (kt + 2 < KT) load_tile(kt + 2, (kt + 2) % STAGES);

        const uint32_t stA = sbase + (uint32_t)(kt % STAGES) * STAGE;
        const uint32_t stB = stA + AB;

#pragma unroll
        for (int ks = 0; ks < 4; ++ks) {
            uint32_t a[4][4], b[2][4];
#pragma unroll
            for (int mt = 0; mt < 4; ++mt) {
                int r = a_row + mt * 16;
                int c = ks * 2 + a_chk0;
                uint32_t ad = stA + (uint32_t)(r * 128 + ((c ^ (r & 7)) << 4));
                LDSM_X4(a[mt][0], a[mt][1], a[mt][2], a[mt][3], ad);
            }
#pragma unroll
            for (int nt2 = 0; nt2 < 2; ++nt2) {
                int r = b_row + nt2 * 16;
                int c = ks * 2 + b_chk0;
                uint32_t bd = stB + (uint32_t)(r * 128 + ((c ^ (r & 7)) << 4));
                LDSM_X4(b[nt2][0], b[nt2][1], b[nt2][2], b[nt2][3], bd);
            }
#pragma unroll
            for (int mt = 0; mt < 4; ++mt)
#pragma unroll
                for (int nt = 0; nt < 4; ++nt)
                    MMA16816(acc[mt][nt], a[mt], b[nt >> 1][(nt & 1) * 2], b[nt >> 1][(nt & 1) * 2 + 1]);
        }
    }

    // ---- epilogue (all paths smem-staged) ----
    if (OP == 3) {
        // stage fp32 acc+bias; writer adds fp16 x1 and streams float4 rows.
        constexpr int OSTRF = 132;   // floats per row (528B)
        float* sOutF = (float*)smem;
        __syncthreads();
#pragma unroll
        for (int mt = 0; mt < 4; ++mt) {
            int row_lo = wm * 64 + mt * 16 + grp;
#pragma unroll
            for (int nt = 0; nt < 4; ++nt) {
                int col = wn * 32 + nt * 8 + 2 * tig;
                float b0 = bias[n0 + col], b1 = bias[n0 + col + 1];
                *(float2*)(sOutF + row_lo * OSTRF + col) =
                    make_float2(acc[mt][nt][0] + b0, acc[mt][nt][1] + b1);
                *(float2*)(sOutF + (row_lo + 8) * OSTRF + col) =
                    make_float2(acc[mt][nt][2] + b0, acc[mt][nt][3] + b1);
            }
        }
        __syncthreads();
#pragma unroll
        for (int i = 0; i < 16; i++) {
            int id  = i * 256 + tid;         // 4096 chunks of 16B
            int row = id >> 5, c4 = id & 31;
            int col = c4 * 4;
            float4 v = *(const float4*)(sOutF + row * OSTRF + col);
            size_t o = (size_t)(m0 + row) * NTOT + n0 + col;
            uint2 u = *(const uint2*)(g_XN1 + o);
            const __half2* hp = (const __half2*)&u;
            float2 x0 = __half22float2(hp[0]);
            float2 x1 = __half22float2(hp[1]);
            v.x += x0.x; v.y += x0.y; v.z += x1.x; v.w += x1.y;
            *(float4*)(outp + o) = v;
        }
    } else {
        constexpr int OSTR = 136;
        __half* sOut = (__half*)smem;
        __syncthreads();
#pragma unroll
        for (int mt = 0; mt < 4; ++mt) {
            int row_lo = wm * 64 + mt * 16 + grp;
#pragma unroll
            for (int nt = 0; nt < 4; ++nt) {
                int col = wn * 32 + nt * 8 + 2 * tig;
                float b0 = bias[n0 + col], b1 = bias[n0 + col + 1];
                float v00 = acc[mt][nt][0] + b0;
                float v01 = acc[mt][nt][1] + b1;
                float v10 = acc[mt][nt][2] + b0;
                float v11 = acc[mt][nt][3] + b1;
                if (OP == 2) {
                    v00 = gelu_f(v00); v01 = gelu_f(v01);
                    v10 = gelu_f(v10); v11 = gelu_f(v11);
                }
                *(__half2*)(sOut + row_lo * OSTR + col)       = __floats2half2_rn(v00, v01);
                *(__half2*)(sOut + (row_lo + 8) * OSTR + col) = __floats2half2_rn(v10, v11);
            }
        }
        __syncthreads();
        if (OP == 1) {
            // coalesced: add fp32 x[remap] row segments, write fp16 x1 rows.
#pragma unroll
            for (int i = 0; i < 8; i++) {
                int id  = i * 256 + tid;     // 2048 chunks of 16B
                int row = id >> 4, c16 = id & 15;
                size_t dimg = win_to_img(m0 + row) * DIMC + n0 + c16 * 8;
                uint4 v = *(const uint4*)(sOut + row * OSTR + c16 * 8);
                const __half2* hv = (const __half2*)&v;
                float4 a0 = *(const float4*)(aux + dimg);
                float4 a1 = *(const float4*)(aux + dimg + 4);
                float2 f0 = __half22float2(hv[0]);
                float2 f1 = __half22float2(hv[1]);
                float2 f2 = __half22float2(hv[2]);
                float2 f3 = __half22float2(hv[3]);
                uint4 o;
                o.x = h2bits(a0.x + f0.x, a0.y + f0.y);
                o.y = h2bits(a0.z + f1.x, a0.w + f1.y);
                o.z = h2bits(a1.x + f2.x, a1.y + f2.y);
                o.w = h2bits(a1.z + f3.x, a1.w + f3.y);
                *(uint4*)(g_XN1 + dimg) = o;
            }
        } else {
            __half* dst = (OP == 0) ? g_QKV : g_H1;
#pragma unroll
            for (int i = 0; i < 8; i++) {
                int id  = i * 256 + tid;
                int row = id >> 4, c16 = id & 15;
                uint4 v = *(const uint4*)(sOut + row * OSTR + c16 * 8);
                *(uint4*)(dst + (size_t)(m0 + row) * NTOT + n0 + c16 * 8) = v;
            }
        }
    }
}

// ---------------- attention via mma.sync: one 128-thread block per (win,head)
// [R11 proven configuration]
__global__ void __launch_bounds__(128) attn_kernel() {
    __shared__ __align__(16) __half sQ[64 * 32];
    __shared__ __align__(16) __half sK[64 * 32];
    __shared__ __align__(16) __half sV[64 * 32];
    __shared__ float srpb[225];
    __shared__ int   slab[64];

    const int bh   = blockIdx.x;
    const int b_   = bh >> 4;
    const int h    = bh & 15;
    const int tid  = threadIdx.x;
    const int w    = tid >> 5;
    const int lane = tid & 31;
    const int grp  = lane >> 2;
    const int tig  = lane & 3;

    const uint32_t qb = smem_u32(sQ);
    const uint32_t kb = smem_u32(sK);
    const uint32_t vb = smem_u32(sV);

    auto qk_off = [](int r, int g) -> uint32_t {
        return (uint32_t)((r >> 1) * 128 + (((((r & 1) << 2) | g) ^ ((r >> 1) & 7)) << 4));
    };

    const __half* base = g_QKV + (size_t)(b_ * 64) * (3 * DIMC) + h * 32;
#pragma unroll
    for (int i = 0; i < 2; i++) {
        int idx = i * 128 + tid;
        int r = idx >> 2, g = idx & 3;
        const __half* rowp = base + (size_t)r * (3 * DIMC);
        uint32_t off = qk_off(r, g);
        *(uint4*)((char*)sQ + off) = *(const uint4*)(rowp + g * 8);
        *(uint4*)((char*)sK + off) = *(const uint4*)(rowp + DIMC + g * 8);
        *(uint4*)((char*)sV + off) = *(const uint4*)(rowp + 2 * DIMC + g * 8);
    }
    if (tid < 64) {
        int widx = b_ & 63;
        int gh = ((widx >> 3) << 3) + (tid >> 3);
        int gw = ((widx & 7) << 3) + (tid & 7);
        int zh = gh < 56 ? 0 : (gh < 60 ? 1 : 2);
        int zw = gw < 56 ? 0 : (gw < 60 ? 1 : 2);
        slab[tid] = zh * 3 + zw;
    }
    for (int i = tid; i < 225; i += 128) srpb[i] = g_RPBt[h * 225 + i];
    __syncthreads();

    float s[8][4];
#pragma unroll
    for (int i = 0; i < 8; i++)
#pragma unroll
        for (int j = 0; j < 4; j++) s[i][j] = 0.f;

    const int a_row  = w * 16 + (lane & 15);
    const int a_chk0 = lane >> 4;
    const int b_row  = (lane & 7) + ((lane >> 4) << 3);
    const int b_chk0 = (lane >> 3) & 1;

#pragma unroll
    for (int ks = 0; ks < 2; ++ks) {
        uint32_t a[4], b[4][4];
        LDSM_X4(a[0], a[1], a[2], a[3], qb + qk_off(a_row, ks * 2 + a_chk0));
#pragma unroll
        for (int nt2 = 0; nt2 < 4; ++nt2)
            LDSM_X4(b[nt2][0], b[nt2][1], b[nt2][2], b[nt2][3],
                    kb + qk_off(nt2 * 16 + b_row, ks * 2 + b_chk0));
#pragma unroll
        for (int nt = 0; nt < 8; ++nt)
            MMA16816(s[nt], a, b[nt >> 1][(nt & 1) * 2], b[nt >> 1][(nt & 1) * 2 + 1]);
    }

    const float scale = 0.17677669529663687f;
    const int r0 = w * 16 + grp;
    const int r1 = r0 + 8;
    const int rh0 = r0 >> 3, rw0 = r0 & 7;
    const int rh1 = r1 >> 3;
    const int lab0 = slab[r0], lab1 = slab[r1];

    float sum0 = 0.f, sum1 = 0.f;
#pragma unroll
    for (int nt = 0; nt < 8; ++nt) {
#pragma unroll
        for (int e = 0; e < 2; ++e) {
            int c  = nt * 8 + tig * 2 + e;
            int mh = c >> 3, mw = c & 7;
            int lb = slab[c];
            float bi0 = srpb[(rh0 - mh + 7) * 15 + (rw0 - mw + 7)];
            float bi1 = srpb[(rh1 - mh + 7) * 15 + (rw0 - mw + 7)];
            float v0 = s[nt][e]     * scale + bi0 + (lab0 == lb ? 0.f : -100.f);
            float v1 = s[nt][2 + e] * scale + bi1 + (lab1 == lb ? 0.f : -100.f);
            float e0 = __expf(v0);
            float e1 = __expf(v1);
            s[nt][e]     = e0;
            s[nt][2 + e] = e1;
            sum0 += e0;
            sum1 += e1;
        }
    }
    sum0 += __shfl_xor_sync(0xffffffffu, sum0, 1);
    sum0 += __shfl_xor_sync(0xffffffffu, sum0, 2);
    sum1 += __shfl_xor_sync(0xffffffffu, sum1, 1);
    sum1 += __shfl_xor_sync(0xffffffffu, sum1, 2);

    float o[4][4];
#pragma unroll
    for (int i = 0; i < 4; i++)
#pragma unroll
        for (int j = 0; j < 4; j++) o[i][j] = 0.f;

#pragma unroll
    for (int ks2 = 0; ks2 < 4; ++ks2) {
        uint32_t pa[4];
        pa[0] = h2bits(s[ks2 * 2][0],     s[ks2 * 2][1]);
        pa[1] = h2bits(s[ks2 * 2][2],     s[ks2 * 2][3]);
        pa[2] = h2bits(s[ks2 * 2 + 1][0], s[ks2 * 2 + 1][1]);
        pa[3] = h2bits(s[ks2 * 2 + 1][2], s[ks2 * 2 + 1][3]);
        int vrow = ks2 * 16 + (lane & 15);
        uint32_t bv0[4], bv1[4];
        LDSM_X4_T(bv0[0], bv0[1], bv0[2], bv0[3], vb + qk_off(vrow, lane >> 4));
        LDSM_X4_T(bv1[0], bv1[1], bv1[2], bv1[3], vb + qk_off(vrow, 2 + (lane >> 4)));
        MMA16816(o[0], pa, bv0[0], bv0[1]);
        MMA16816(o[1], pa, bv0[2], bv0[3]);
        MMA16816(o[2], pa, bv1[0], bv1[1]);
        MMA16816(o[3], pa, bv1[2], bv1[3]);
    }

    const float inv0 = 1.f / sum0;
    const float inv1 = 1.f / sum1;
    __half* o0 = g_O + (size_t)(b_ * 64 + r0) * DIMC + h * 32;
    __half* o1 = g_O + (size_t)(b_ * 64 + r1) * DIMC + h * 32;
#pragma unroll
    for (int nt = 0; nt < 4; ++nt) {
        int d = nt * 8 + tig * 2;
        *(__half2*)(o0 + d) = __floats2half2_rn(o[nt][0] * inv0, o[nt][1] * inv0);
        *(__half2*)(o1 + d) = __floats2half2_rn(o[nt][2] * inv1, o[nt][3] * inv1);
    }
}

// ---------------- host launcher ----------------
extern "C" void kernel_launch(void* const* d_in, const int* in_sizes, int n_in,
                              void* d_out, int out_size) {
    const float* x      = (const float*)d_in[0];
    const float* n1g    = (const float*)d_in[1];
    const float* n1b    = (const float*)d_in[2];
    const float* qkv_w  = (const float*)d_in[3];
    const float* qkv_b  = (const float*)d_in[4];
    const float* proj_w = (const float*)d_in[5];
    const float* proj_b = (const float*)d_in[6];
    const float* rpb    = (const float*)d_in[7];
    const float* n2g    = (const float*)d_in[8];
    const float* n2b    = (const float*)d_in[9];
    const float* fc1_w  = (const float*)d_in[10];
    const float* fc1_b  = (const float*)d_in[11];
    const float* fc2_w  = (const float*)d_in[12];
    const float* fc2_b  = (const float*)d_in[13];
    float* out = (float*)d_out;

    constexpr int SMEMB = 3 * (128 * 64 * 2 + 128 * 64 * 2);  // 98304 bytes

    cudaFuncSetAttribute(gemm_f16<1536, 512, 0>, cudaFuncAttributeMaxDynamicSharedMemorySize, SMEMB);
    cudaFuncSetAttribute(gemm_f16<512,  512, 1>, cudaFuncAttributeMaxDynamicSharedMemorySize, SMEMB);
    cudaFuncSetAttribute(gemm_f16<2048, 512, 2>, cudaFuncAttributeMaxDynamicSharedMemorySize, SMEMB);
    cudaFuncSetAttribute(gemm_f16<512, 2048, 3>, cudaFuncAttributeMaxDynamicSharedMemorySize, SMEMB);

    // weights -> fp16 copies + rpb transpose (single kernel)
    cvt_all<<<(NW1 + 255) / 256, 256>>>(qkv_w, proj_w, fc1_w, fc2_w, rpb);

    // LN1 + shift + window partition -> g_XN1 (window order)
    ln1_kernel<<<MROWS / 8, 256>>>(x, n1g, n1b);

    // QKV projection
    gemm_f16<1536, 512, 0><<<dim3(1536 / 128, MROWS / 128), 256, SMEMB>>>(qkv_b, nullptr, nullptr);

    // windowed attention (tensor-core)
    attn_kernel<<<BWIN * NHEADS, 128>>>();

    // output projection + window reverse + shift + residual -> g_XN1 (x1, fp16)
    gemm_f16<512, 512, 1><<<dim3(512 / 128, MROWS / 128), 256, SMEMB>>>(proj_b, x, nullptr);

    // LN2 (reads fp16 x1)
    ln2_kernel<<<MROWS / 8, 256>>>(n2g, n2b);

    // FC1 + gelu
    gemm_f16<2048, 512, 2><<<dim3(2048 / 128, MROWS / 128), 256, SMEMB>>>(fc1_b, nullptr, nullptr);

    // FC2 + residual: out = x1 + acc + bias (write-only fp32)
    gemm_f16<512, 2048, 3><<<dim3(512 / 128, MROWS / 128), 256, SMEMB>>>(fc2_b, nullptr, out);
}

// round 14
// speedup vs baseline: 1.0311x; 1.0059x over previous
#include <cuda_runtime.h>
#include <cuda_fp16.h>
#include <cstdint>

// ---------------- problem constants ----------------
#define DIMC   512
#define NHEADS 16
#define SSZ    4
#define BWIN   2048          // 32 batches * 64 windows
#define MROWS  131072        // BWIN * 64 == B*L
#define CHID   2048          // mlp hidden

// ---------------- scratch (device globals; no allocs allowed) ----------------
__device__ __half g_XN1[(size_t)MROWS * DIMC];
__device__ __half g_QKV[(size_t)MROWS * 3 * DIMC];
__device__ __half g_O  [(size_t)MROWS * DIMC];
__device__ __half g_XN2[(size_t)MROWS * DIMC];
__device__ __half g_H1 [(size_t)MROWS * CHID];
__device__ __half g_Wq [3 * DIMC * DIMC];
__device__ __half g_Wp [DIMC * DIMC];
__device__ __half g_W1 [CHID * DIMC];
__device__ __half g_W2 [DIMC * CHID];
__device__ float  g_RPBt[NHEADS * 225];   // transposed rel-pos bias

#define NWQ (3 * DIMC * DIMC)
#define NWP (DIMC * DIMC)
#define NW1 (CHID * DIMC)
#define NW2 (DIMC * CHID)

// ---------------- helpers ----------------
// fast GELU: tanh form via sigmoid; |err| < 1e-4 over the FC1 activation range
__device__ __forceinline__ float gelu_f(float x) {
    float t = x * (0.7978845608f + 0.0356774081f * x * x);
    return x * __frcp_rn(1.f + __expf(-2.f * t));
}

__device__ __forceinline__ uint32_t smem_u32(const void* p) {
    return (uint32_t)__cvta_generic_to_shared(p);
}

// token index in window order -> token index in (B,H,W) order (shift mapping)
__device__ __forceinline__ size_t win_to_img(int t) {
    int b_   = t >> 6, nn = t & 63;
    int bimg = b_ >> 6, widx = b_ & 63;
    int gh = ((widx >> 3) << 3) + (nn >> 3);
    int gw = ((widx & 7) << 3) + (nn & 7);
    int sh = (gh + SSZ) & 63;
    int sw = (gw + SSZ) & 63;
    return ((size_t)bimg << 12) + (size_t)(sh << 6) + (size_t)sw;
}

#define LDSM_X4(r0, r1, r2, r3, addr)                                          \
    asm volatile("ldmatrix.sync.aligned.m8n8.x4.shared.b16 {%0,%1,%2,%3}, [%4];" \
                 : "=r"(r0), "=r"(r1), "=r"(r2), "=r"(r3) : "r"(addr))

#define LDSM_X4_T(r0, r1, r2, r3, addr)                                        \
    asm volatile("ldmatrix.sync.aligned.m8n8.x4.trans.shared.b16 {%0,%1,%2,%3}, [%4];" \
                 : "=r"(r0), "=r"(r1), "=r"(r2), "=r"(r3) : "r"(addr))

#define MMA16816(d, a, b0, b1)                                                 \
    asm volatile(                                                              \
        "mma.sync.aligned.m16n8k16.row.col.f32.f16.f16.f32 "                   \
        "{%0,%1,%2,%3},{%4,%5,%6,%7},{%8,%9},{%0,%1,%2,%3};"                   \
        : "+f"((d)[0]), "+f"((d)[1]), "+f"((d)[2]), "+f"((d)[3])               \
        : "r"((a)[0]), "r"((a)[1]), "r"((a)[2]), "r"((a)[3]),                  \
          "r"(b0), "r"(b1))

__device__ __forceinline__ uint32_t h2bits(float x, float y) {
    __half2 h = __floats2half2_rn(x, y);
    return *(uint32_t*)&h;
}

// ---------------- weight convert + rpb transpose ----------------
__global__ void cvt_all(const float* __restrict__ wq, const float* __restrict__ wp,
                        const float* __restrict__ w1, const float* __restrict__ w2,
                        const float* __restrict__ rpb) {
    int i = blockIdx.x * 256 + threadIdx.x;
    if (i < NWQ) g_Wq[i] = __float2half(wq[i]);
    if (i < NWP) g_Wp[i] = __float2half(wp[i]);
    if (i < NW1) g_W1[i] = __float2half(w1[i]);
    if (i < NW2) g_W2[i] = __float2half(w2[i]);
    if (i < NHEADS * 225) {
        int h = i / 225, j = i % 225;
        g_RPBt[i] = rpb[j * NHEADS + h];
    }
}

// ---------------- LN1 (fp32 input, shift+window remap) ----------------
__global__ void __launch_bounds__(256) ln1_kernel(const float* __restrict__ xin,
                                                  const float* __restrict__ gamma,
                                                  const float* __restrict__ beta) {
    int t    = (blockIdx.x * 256 + threadIdx.x) >> 5;
    int lane = threadIdx.x & 31;

    size_t src = win_to_img(t);
    const float* row = xin + src * DIMC;

    float4 v[4];
    float sum = 0.f, sq = 0.f;
#pragma unroll
    for (int p = 0; p < 4; p++) {
        v[p] = *(const float4*)(row + p * 128 + lane * 4);
        sum += v[p].x + v[p].y + v[p].z + v[p].w;
        sq  += v[p].x * v[p].x + v[p].y * v[p].y + v[p].z * v[p].z + v[p].w * v[p].w;
    }
#pragma unroll
    for (int o = 16; o > 0; o >>= 1) {
        sum += __shfl_xor_sync(0xffffffffu, sum, o);
        sq  += __shfl_xor_sync(0xffffffffu, sq, o);
    }
    float mu   = sum * (1.f / 512.f);
    float var  = sq * (1.f / 512.f) - mu * mu;
    float rstd = rsqrtf(var + 1e-5f);

    __half* orow = g_XN1 + (size_t)t * DIMC;
#pragma unroll
    for (int p = 0; p < 4; p++) {
        int c = p * 128 + lane * 4;
        float4 g4 = *(const float4*)(gamma + c);
        float4 b4 = *(const float4*)(beta + c);
        __half2 h0 = __floats2half2_rn((v[p].x - mu) * rstd * g4.x + b4.x,
                                       (v[p].y - mu) * rstd * g4.y + b4.y);
        __half2 h1 = __floats2half2_rn((v[p].z - mu) * rstd * g4.z + b4.z,
                                       (v[p].w - mu) * rstd * g4.w + b4.w);
        uint2 u;
        u.x = *(uint32_t*)&h0;
        u.y = *(uint32_t*)&h1;
        *(uint2*)(orow + c) = u;
    }
}

// ---------------- LN2 (fp16 x1 input from g_XN1, image order) ---------------
__global__ void __launch_bounds__(256) ln2_kernel(const float* __restrict__ gamma,
                                                  const float* __restrict__ beta) {
    int t    = (blockIdx.x * 256 + threadIdx.x) >> 5;
    int lane = threadIdx.x & 31;

    const __half* row = g_XN1 + (size_t)t * DIMC;

    float v[16];
    float sum = 0.f, sq = 0.f;
#pragma unroll
    for (int p = 0; p < 4; p++) {
        uint2 u = *(const uint2*)(row + p * 128 + lane * 4);
        const __half2* hp = (const __half2*)&u;
        float2 f0 = __half22float2(hp[0]);
        float2 f1 = __half22float2(hp[1]);
        v[p * 4]     = f0.x; v[p * 4 + 1] = f0.y;
        v[p * 4 + 2] = f1.x; v[p * 4 + 3] = f1.y;
        sum += f0.x + f0.y + f1.x + f1.y;
        sq  += f0.x * f0.x + f0.y * f0.y + f1.x * f1.x + f1.y * f1.y;
    }
#pragma unroll
    for (int o = 16; o > 0; o >>= 1) {
        sum += __shfl_xor_sync(0xffffffffu, sum, o);
        sq  += __shfl_xor_sync(0xffffffffu, sq, o);
    }
    float mu   = sum * (1.f / 512.f);
    float var  = sq * (1.f / 512.f) - mu * mu;
    float rstd = rsqrtf(var + 1e-5f);

    __half* orow = g_XN2 + (size_t)t * DIMC;
#pragma unroll
    for (int p = 0; p < 4; p++) {
        int c = p * 128 + lane * 4;
        float4 g4 = *(const float4*)(gamma + c);
        float4 b4 = *(const float4*)(beta + c);
        __half2 h0 = __floats2half2_rn((v[p * 4]     - mu) * rstd * g4.x + b4.x,
                                       (v[p * 4 + 1] - mu) * rstd * g4.y + b4.y);
        __half2 h1 = __floats2half2_rn((v[p * 4 + 2] - mu) * rstd * g4.z + b4.z,
                                       (v[p * 4 + 3] - mu) * rstd * g4.w + b4.w);
        uint2 u;
        u.x = *(uint32_t*)&h0;
        u.y = *(uint32_t*)&h1;
        *(uint2*)(orow + c) = u;
    }
}

// ---------------- fp16 mma.sync GEMM: C[M,N] = A[M,K] @ W[N,K]^T ------------
// BM=128, BN=128, BK=64, 3-stage cp.async, XOR-8 swizzle, 8 warps of 64x32.
// ALL epilogues smem-staged for coalesced global traffic.
template <int NTOT, int KTOT, int OP>
__global__ void __launch_bounds__(256, 2) gemm_f16(const float* __restrict__ bias,
                                                   const float* __restrict__ aux,
                                                   float* __restrict__ outp) {
    constexpr int BM = 128, BN = 128, BK = 64, STAGES = 3;
    constexpr int KT = KTOT / BK;
    constexpr uint32_t AB    = BM * BK * 2;   // 16KB
    constexpr uint32_t BB    = BN * BK * 2;   // 16KB
    constexpr uint32_t STAGE = AB + BB;       // 32KB

    extern __shared__ char smem[];
    const uint32_t sbase = smem_u32(smem);
    const int tid = threadIdx.x;

    const __half* A;
    const __half* Bw;
    if (OP == 0)      { A = g_XN1; Bw = g_Wq; }
    else if (OP == 1) { A = g_O;   Bw = g_Wp; }
    else if (OP == 2) { A = g_XN2; Bw = g_W1; }
    else              { A = g_H1;  Bw = g_W2; }

    const int m0 = blockIdx.y * BM;
    const int n0 = blockIdx.x * BN;

    auto load_tile = [&](int kt, int s) {
        const __half* gA = A + (size_t)m0 * KTOT + kt * BK;
        const __half* gB = Bw + (size_t)n0 * KTOT + kt * BK;
#pragma unroll
        for (int i = 0; i < 4; i++) {
            int idx = i * 256 + tid;
            int r = idx >> 3, g = idx & 7;
            uint32_t off = (uint32_t)(r * 128 + ((g ^ (r & 7)) << 4));
            uint32_t da = sbase + (uint32_t)s * STAGE + off;
            const __half* pa = gA + (size_t)r * KTOT + g * 8;
            asm volatile("cp.async.cg.shared.global [%0], [%1], 16;\n" ::"r"(da), "l"(pa));
            uint32_t db = sbase + (uint32_t)s * STAGE + AB + off;
            const __half* pb = gB + (size_t)r * KTOT + g * 8;
            asm volatile("cp.async.cg.shared.global [%0], [%1], 16;\n" ::"r"(db), "l"(pb));
        }
        asm volatile("cp.async.commit_group;\n");
    };

    const int w    = tid >> 5;
    const int wm   = w >> 2;
    const int wn   = w & 3;
    const int lane = tid & 31;
    const int grp  = lane >> 2;
    const int tig  = lane & 3;

    float acc[4][4][4];
#pragma unroll
    for (int i = 0; i < 4; i++)
#pragma unroll
        for (int j = 0; j < 4; j++)
#pragma unroll
            for (int r = 0; r < 4; r++) acc[i][j][r] = 0.f;

    const int a_row  = wm * 64 + (lane & 15);
    const int a_chk0 = lane >> 4;
    const int b_row  = wn * 32 + (lane & 7) + ((lane >> 4) << 3);
    const int b_chk0 = (lane >> 3) & 1;

    load_tile(0, 0);
    load_tile(1, 1);

#pragma unroll 1
    for (int kt = 0; kt < KT; ++kt) {
        if (kt + 2 < KT) asm volatile("cp.async.wait_group 1;\n");
        else             asm volatile("cp.async.wait_group 0;\n");
        __syncthreads();

        if (kt + 2 < KT) load_tile(kt + 2, (kt + 2) % STAGES);

        const uint32_t stA = sbase + (uint32_t)(kt % STAGES) * STAGE;
        const uint32_t stB = stA + AB;

#pragma unroll
        for (int ks = 0; ks < 4; ++ks) {
            uint32_t a[4][4], b[2][4];
#pragma unroll
            for (int mt = 0; mt < 4; ++mt) {
                int r = a_row + mt * 16;
                int c = ks * 2 + a_chk0;
                uint32_t ad = stA + (uint32_t)(r * 128 + ((c ^ (r & 7)) << 4));
                LDSM_X4(a[mt][0], a[mt][1], a[mt][2], a[mt][3], ad);
            }
#pragma unroll
            for (int nt2 = 0; nt2 < 2; ++nt2) {
                int r = b_row + nt2 * 16;
                int c = ks * 2 + b_chk0;
                uint32_t bd = stB + (uint32_t)(r * 128 + ((c ^ (r & 7)) << 4));
                LDSM_X4(b[nt2][0], b[nt2][1], b[nt2][2], b[nt2][3], bd);
            }
#pragma unroll
            for (int mt = 0; mt < 4; ++mt)
#pragma unroll
                for (int nt = 0; nt < 4; ++nt)
                    MMA16816(acc[mt][nt], a[mt], b[nt >> 1][(nt & 1) * 2], b[nt >> 1][(nt & 1) * 2 + 1]);
        }
    }

    // ---- epilogue (all paths smem-staged) ----
    if (OP == 3) {
        constexpr int OSTRF = 132;   // floats per row (528B)
        float* sOutF = (float*)smem;
        __syncthreads();
#pragma unroll
        for (int mt = 0; mt < 4; ++mt) {
            int row_lo = wm * 64 + mt * 16 + grp;
#pragma unroll
            for (int nt = 0; nt < 4; ++nt) {
                int col = wn * 32 + nt * 8 + 2 * tig;
                float b0 = bias[n0 + col], b1 = bias[n0 + col + 1];
                *(float2*)(sOutF + row_lo * OSTRF + col) =
                    make_float2(acc[mt][nt][0] + b0, acc[mt][nt][1] + b1);
                *(float2*)(sOutF + (row_lo + 8) * OSTRF + col) =
                    make_float2(acc[mt][nt][2] + b0, acc[mt][nt][3] + b1);
            }
        }
        __syncthreads();
#pragma unroll
        for (int i = 0; i < 16; i++) {
            int id  = i * 256 + tid;
            int row = id >> 5, c4 = id & 31;
            int col = c4 * 4;
            float4 v = *(const float4*)(sOutF + row * OSTRF + col);
            size_t o = (size_t)(m0 + row) * NTOT + n0 + col;
            uint2 u = *(const uint2*)(g_XN1 + o);
            const __half2* hp = (const __half2*)&u;
            float2 x0 = __half22float2(hp[0]);
            float2 x1 = __half22float2(hp[1]);
            v.x += x0.x; v.y += x0.y; v.z += x1.x; v.w += x1.y;
            *(float4*)(outp + o) = v;
        }
    } else {
        constexpr int OSTR = 136;
        __half* sOut = (__half*)smem;
        __syncthreads();
#pragma unroll
        for (int mt = 0; mt < 4; ++mt) {
            int row_lo = wm * 64 + mt * 16 + grp;
#pragma unroll
            for (int nt = 0; nt < 4; ++nt) {
                int col = wn * 32 + nt * 8 + 2 * tig;
                float b0 = bias[n0 + col], b1 = bias[n0 + col + 1];
                float v00 = acc[mt][nt][0] + b0;
                float v01 = acc[mt][nt][1] + b1;
                float v10 = acc[mt][nt][2] + b0;
                float v11 = acc[mt][nt][3] + b1;
                if (OP == 2) {
                    v00 = gelu_f(v00); v01 = gelu_f(v01);
                    v10 = gelu_f(v10); v11 = gelu_f(v11);
                }
                *(__half2*)(sOut + row_lo * OSTR + col)       = __floats2half2_rn(v00, v01);
                *(__half2*)(sOut + (row_lo + 8) * OSTR + col) = __floats2half2_rn(v10, v11);
            }
        }
        __syncthreads();
        if (OP == 1) {
#pragma unroll
            for (int i = 0; i < 8; i++) {
                int id  = i * 256 + tid;
                int row = id >> 4, c16 = id & 15;
                size_t dimg = win_to_img(m0 + row) * DIMC + n0 + c16 * 8;
                uint4 v = *(const uint4*)(sOut + row * OSTR + c16 * 8);
                const __half2* hv = (const __half2*)&v;
                float4 a0 = *(const float4*)(aux + dimg);
                float4 a1 = *(const float4*)(aux + dimg + 4);
                float2 f0 = __half22float2(hv[0]);
                float2 f1 = __half22float2(hv[1]);
                float2 f2 = __half22float2(hv[2]);
                float2 f3 = __half22float2(hv[3]);
                uint4 o;
                o.x = h2bits(a0.x + f0.x, a0.y + f0.y);
                o.y = h2bits(a0.z + f1.x, a0.w + f1.y);
                o.z = h2bits(a1.x + f2.x, a1.y + f2.y);
                o.w = h2bits(a1.z + f3.x, a1.w + f3.y);
                *(uint4*)(g_XN1 + dimg) = o;
            }
        } else {
            __half* dst = (OP == 0) ? g_QKV : g_H1;
#pragma unroll
            for (int i = 0; i < 8; i++) {
                int id  = i * 256 + tid;
                int row = id >> 4, c16 = id & 15;
                uint4 v = *(const uint4*)(sOut + row * OSTR + c16 * 8);
                *(uint4*)(dst + (size_t)(m0 + row) * NTOT + n0 + c16 * 8) = v;
            }
        }
    }
}

// ---------------- attention via mma.sync: one 128-thread block per (win,head)
// O output staged through smem for coalesced row stores.
__global__ void __launch_bounds__(128) attn_kernel() {
    __shared__ __align__(16) __half sQ[64 * 32];
    __shared__ __align__(16) __half sK[64 * 32];
    __shared__ __align__(16) __half sV[64 * 32];
    __shared__ __align__(16) __half sO[64 * 40];   // staging, stride 40 (conflict-free)
    __shared__ float srpb[225];
    __shared__ int   slab[64];

    const int bh   = blockIdx.x;
    const int b_   = bh >> 4;
    const int h    = bh & 15;
    const int tid  = threadIdx.x;
    const int w    = tid >> 5;
    const int lane = tid & 31;
    const int grp  = lane >> 2;
    const int tig  = lane & 3;

    const uint32_t qb = smem_u32(sQ);
    const uint32_t kb = smem_u32(sK);
    const uint32_t vb = smem_u32(sV);

    auto qk_off = [](int r, int g) -> uint32_t {
        return (uint32_t)((r >> 1) * 128 + (((((r & 1) << 2) | g) ^ ((r >> 1) & 7)) << 4));
    };

    const __half* base = g_QKV + (size_t)(b_ * 64) * (3 * DIMC) + h * 32;
#pragma unroll
    for (int i = 0; i < 2; i++) {
        int idx = i * 128 + tid;
        int r = idx >> 2, g = idx & 3;
        const __half* rowp = base + (size_t)r * (3 * DIMC);
        uint32_t off = qk_off(r, g);
        *(uint4*)((char*)sQ + off) = *(const uint4*)(rowp + g * 8);
        *(uint4*)((char*)sK + off) = *(const uint4*)(rowp + DIMC + g * 8);
        *(uint4*)((char*)sV + off) = *(const uint4*)(rowp + 2 * DIMC + g * 8);
    }
    if (tid < 64) {
        int widx = b_ & 63;
        int gh = ((widx >> 3) << 3) + (tid >> 3);
        int gw = ((widx & 7) << 3) + (tid & 7);
        int zh = gh < 56 ? 0 : (gh < 60 ? 1 : 2);
        int zw = gw < 56 ? 0 : (gw < 60 ? 1 : 2);
        slab[tid] = zh * 3 + zw;
    }
    for (int i = tid; i < 225; i += 128) srpb[i] = g_RPBt[h * 225 + i];
    __syncthreads();

    float s[8][4];
#pragma unroll
    for (int i = 0; i < 8; i++)
#pragma unroll
        for (int j = 0; j < 4; j++) s[i][j] = 0.f;

    const int a_row  = w * 16 + (lane & 15);
    const int a_chk0 = lane >> 4;
    const int b_row  = (lane & 7) + ((lane >> 4) << 3);
    const int b_chk0 = (lane >> 3) & 1;

#pragma unroll
    for (int ks = 0; ks < 2; ++ks) {
        uint32_t a[4], b[4][4];
        LDSM_X4(a[0], a[1], a[2], a[3], qb + qk_off(a_row, ks * 2 + a_chk0));
#pragma unroll
        for (int nt2 = 0; nt2 < 4; ++nt2)
            LDSM_X4(b[nt2][0], b[nt2][1], b[nt2][2], b[nt2][3],
                    kb + qk_off(nt2 * 16 + b_row, ks * 2 + b_chk0));
#pragma unroll
        for (int nt = 0; nt < 8; ++nt)
            MMA16816(s[nt], a, b[nt >> 1][(nt & 1) * 2], b[nt >> 1][(nt & 1) * 2 + 1]);
    }

    const float scale = 0.17677669529663687f;
    const int r0 = w * 16 + grp;
    const int r1 = r0 + 8;
    const int rh0 = r0 >> 3, rw0 = r0 & 7;
    const int rh1 = r1 >> 3;
    const int lab0 = slab[r0], lab1 = slab[r1];

    float sum0 = 0.f, sum1 = 0.f;
#pragma unroll
    for (int nt = 0; nt < 8; ++nt) {
#pragma unroll
        for (int e = 0; e < 2; ++e) {
            int c  = nt * 8 + tig * 2 + e;
            int mh = c >> 3, mw = c & 7;
            int lb = slab[c];
            float bi0 = srpb[(rh0 - mh + 7) * 15 + (rw0 - mw + 7)];
            float bi1 = srpb[(rh1 - mh + 7) * 15 + (rw0 - mw + 7)];
            float v0 = s[nt][e]     * scale + bi0 + (lab0 == lb ? 0.f : -100.f);
            float v1 = s[nt][2 + e] * scale + bi1 + (lab1 == lb ? 0.f : -100.f);
            float e0 = __expf(v0);
            float e1 = __expf(v1);
            s[nt][e]     = e0;
            s[nt][2 + e] = e1;
            sum0 += e0;
            sum1 += e1;
        }
    }
    sum0 += __shfl_xor_sync(0xffffffffu, sum0, 1);
    sum0 += __shfl_xor_sync(0xffffffffu, sum0, 2);
    sum1 += __shfl_xor_sync(0xffffffffu, sum1, 1);
    sum1 += __shfl_xor_sync(0xffffffffu, sum1, 2);

    float o[4][4];
#pragma unroll
    for (int i = 0; i < 4; i++)
#pragma unroll
        for (int j = 0; j < 4; j++) o[i][j] = 0.f;

#pragma unroll
    for (int ks2 = 0; ks2 < 4; ++ks2) {
        uint32_t pa[4];
        pa[0] = h2bits(s[ks2 * 2][0],     s[ks2 * 2][1]);
        pa[1] = h2bits(s[ks2 * 2][2],     s[ks2 * 2][3]);
        pa[2] = h2bits(s[ks2 * 2 + 1][0], s[ks2 * 2 + 1][1]);
        pa[3] = h2bits(s[ks2 * 2 + 1][2], s[ks2 * 2 + 1][3]);
        int vrow = ks2 * 16 + (lane & 15);
        uint32_t bv0[4], bv1[4];
        LDSM_X4_T(bv0[0], bv0[1], bv0[2], bv0[3], vb + qk_off(vrow, lane >> 4));
        LDSM_X4_T(bv1[0], bv1[1], bv1[2], bv1[3], vb + qk_off(vrow, 2 + (lane >> 4)));
        MMA16816(o[0], pa, bv0[0], bv0[1]);
        MMA16816(o[1], pa, bv0[2], bv0[3]);
        MMA16816(o[2], pa, bv1[0], bv1[1]);
        MMA16816(o[3], pa, bv1[2], bv1[3]);
    }

    // ---- stage O in smem, then coalesced row stores ----
    const float inv0 = 1.f / sum0;
    const float inv1 = 1.f / sum1;
#pragma unroll
    for (int nt = 0; nt < 4; ++nt) {
        int d = nt * 8 + tig * 2;
        *(__half2*)(sO + r0 * 40 + d) = __floats2half2_rn(o[nt][0] * inv0, o[nt][1] * inv0);
        *(__half2*)(sO + r1 * 40 + d) = __floats2half2_rn(o[nt][2] * inv1, o[nt][3] * inv1);
    }
    __syncthreads();
    __half* obase = g_O + (size_t)(b_ * 64) * DIMC + h * 32;
#pragma unroll
    for (int i = 0; i < 2; i++) {
        int idx = i * 128 + tid;            // 256 chunks of 16B
        int row = idx >> 2, ch = idx & 3;
        uint4 v = *(const uint4*)(sO + row * 40 + ch * 8);
        *(uint4*)(obase + (size_t)row * DIMC + ch * 8) = v;
    }
}

// ---------------- host launcher ----------------
extern "C" void kernel_launch(void* const* d_in, const int* in_sizes, int n_in,
                              void* d_out, int out_size) {
    const float* x      = (const float*)d_in[0];
    const float* n1g    = (const float*)d_in[1];
    const float* n1b    = (const float*)d_in[2];
    const float* qkv_w  = (const float*)d_in[3];
    const float* qkv_b  = (const float*)d_in[4];
    const float* proj_w = (const float*)d_in[5];
    const float* proj_b = (const float*)d_in[6];
    const float* rpb    = (const float*)d_in[7];
    const float* n2g    = (const float*)d_in[8];
    const float* n2b    = (const float*)d_in[9];
    const float* fc1_w  = (const float*)d_in[10];
    const float* fc1_b  = (const float*)d_in[11];
    const float* fc2_w  = (const float*)d_in[12];
    const float* fc2_b  = (const float*)d_in[13];
    float* out = (float*)d_out;

    constexpr int SMEMB = 3 * (128 * 64 * 2 + 128 * 64 * 2);  // 98304 bytes

    cudaFuncSetAttribute(gemm_f16<1536, 512, 0>, cudaFuncAttributeMaxDynamicSharedMemorySize, SMEMB);
    cudaFuncSetAttribute(gemm_f16<512,  512, 1>, cudaFuncAttributeMaxDynamicSharedMemorySize, SMEMB);
    cudaFuncSetAttribute(gemm_f16<2048, 512, 2>, cudaFuncAttributeMaxDynamicSharedMemorySize, SMEMB);
    cudaFuncSetAttribute(gemm_f16<512, 2048, 3>, cudaFuncAttributeMaxDynamicSharedMemorySize, SMEMB);

    // weights -> fp16 copies + rpb transpose (single kernel)
    cvt_all<<<(NW1 + 255) / 256, 256>>>(qkv_w, proj_w, fc1_w, fc2_w, rpb);

    // LN1 + shift + window partition -> g_XN1 (window order)
    ln1_kernel<<<MROWS / 8, 256>>>(x, n1g, n1b);

    // QKV projection
    gemm_f16<1536, 512, 0><<<dim3(1536 / 128, MROWS / 128), 256, SMEMB>>>(qkv_b, nullptr, nullptr);

    // windowed attention (tensor-core)
    attn_kernel<<<BWIN * NHEADS, 128>>>();

    // output projection + window reverse + shift + residual -> g_XN1 (x1, fp16)
    gemm_f16<512, 512, 1><<<dim3(512 / 128, MROWS / 128), 256, SMEMB>>>(proj_b, x, nullptr);

    // LN2 (reads fp16 x1)
    ln2_kernel<<<MROWS / 8, 256>>>(n2g, n2b);

    // FC1 + gelu (fast tanh-form)
    gemm_f16<2048, 512, 2><<<dim3(2048 / 128, MROWS / 128), 256, SMEMB>>>(fc1_b, nullptr, nullptr);

    // FC2 + residual: out = x1 + acc + bias (write-only fp32)
    gemm_f16<512, 2048, 3><<<dim3(512 / 128, MROWS / 128), 256, SMEMB>>>(fc2_b, nullptr, out);
}

// round 15
// speedup vs baseline: 1.0359x; 1.0046x over previous
#include <cuda_runtime.h>
#include <cuda_fp16.h>
#include <cstdint>

// ---------------- problem constants ----------------
#define DIMC   512
#define NHEADS 16
#define SSZ    4
#define BWIN   2048          // 32 batches * 64 windows
#define MROWS  131072        // BWIN * 64 == B*L
#define CHID   2048          // mlp hidden

// ---------------- scratch (device globals; no allocs allowed) ----------------
__device__ __half g_XN1[(size_t)MROWS * DIMC];
__device__ __half g_QKV[(size_t)MROWS * 3 * DIMC];
__device__ __half g_O  [(size_t)MROWS * DIMC];
__device__ __half g_XN2[(size_t)MROWS * DIMC];
__device__ __half g_H1 [(size_t)MROWS * CHID];
__device__ __half g_Wq [3 * DIMC * DIMC];
__device__ __half g_Wp [DIMC * DIMC];
__device__ __half g_W1 [CHID * DIMC];
__device__ __half g_W2 [DIMC * CHID];
__device__ float  g_RPBt[NHEADS * 225];   // transposed rel-pos bias

#define NWQ (3 * DIMC * DIMC)
#define NWP (DIMC * DIMC)
#define NW1 (CHID * DIMC)
#define NW2 (DIMC * CHID)

// ---------------- helpers ----------------
// fast GELU: tanh form via sigmoid; |err| < 1e-4 over the FC1 activation range
__device__ __forceinline__ float gelu_f(float x) {
    float t = x * (0.7978845608f + 0.0356774081f * x * x);
    return x * __frcp_rn(1.f + __expf(-2.f * t));
}

__device__ __forceinline__ uint32_t smem_u32(const void* p) {
    return (uint32_t)__cvta_generic_to_shared(p);
}

// token index in window order -> token index in (B,H,W) order (shift mapping)
__device__ __forceinline__ size_t win_to_img(int t) {
    int b_   = t >> 6, nn = t & 63;
    int bimg = b_ >> 6, widx = b_ & 63;
    int gh = ((widx >> 3) << 3) + (nn >> 3);
    int gw = ((widx & 7) << 3) + (nn & 7);
    int sh = (gh + SSZ) & 63;
    int sw = (gw + SSZ) & 63;
    return ((size_t)bimg << 12) + (size_t)(sh << 6) + (size_t)sw;
}

#define LDSM_X4(r0, r1, r2, r3, addr)                                          \
    asm volatile("ldmatrix.sync.aligned.m8n8.x4.shared.b16 {%0,%1,%2,%3}, [%4];" \
                 : "=r"(r0), "=r"(r1), "=r"(r2), "=r"(r3) : "r"(addr))

#define LDSM_X4_T(r0, r1, r2, r3, addr)                                        \
    asm volatile("ldmatrix.sync.aligned.m8n8.x4.trans.shared.b16 {%0,%1,%2,%3}, [%4];" \
                 : "=r"(r0), "=r"(r1), "=r"(r2), "=r"(r3) : "r"(addr))

#define MMA16816(d, a, b0, b1)                                                 \
    asm volatile(                                                              \
        "mma.sync.aligned.m16n8k16.row.col.f32.f16.f16.f32 "                   \
        "{%0,%1,%2,%3},{%4,%5,%6,%7},{%8,%9},{%0,%1,%2,%3};"                   \
        : "+f"((d)[0]), "+f"((d)[1]), "+f"((d)[2]), "+f"((d)[3])               \
        : "r"((a)[0]), "r"((a)[1]), "r"((a)[2]), "r"((a)[3]),                  \
          "r"(b0), "r"(b1))

__device__ __forceinline__ uint32_t h2bits(float x, float y) {
    __half2 h = __floats2half2_rn(x, y);
    return *(uint32_t*)&h;
}

// ---------------- weight convert + rpb transpose ----------------
__global__ void cvt_all(const float* __restrict__ wq, const float* __restrict__ wp,
                        const float* __restrict__ w1, const float* __restrict__ w2,
                        const float* __restrict__ rpb) {
    int i = blockIdx.x * 256 + threadIdx.x;
    if (i < NWQ) g_Wq[i] = __float2half(wq[i]);
    if (i < NWP) g_Wp[i] = __float2half(wp[i]);
    if (i < NW1) g_W1[i] = __float2half(w1[i]);
    if (i < NW2) g_W2[i] = __float2half(w2[i]);
    if (i < NHEADS * 225) {
        int h = i / 225, j = i % 225;
        g_RPBt[i] = rpb[j * NHEADS + h];
    }
}

// ---------------- LN1 (fp32 input, shift+window remap) ----------------
__global__ void __launch_bounds__(256) ln1_kernel(const float* __restrict__ xin,
                                                  const float* __restrict__ gamma,
                                                  const float* __restrict__ beta) {
    int t    = (blockIdx.x * 256 + threadIdx.x) >> 5;
    int lane = threadIdx.x & 31;

    size_t src = win_to_img(t);
    const float* row = xin + src * DIMC;

    float4 v[4];
    float sum = 0.f, sq = 0.f;
#pragma unroll
    for (int p = 0; p < 4; p++) {
        v[p] = *(const float4*)(row + p * 128 + lane * 4);
        sum += v[p].x + v[p].y + v[p].z + v[p].w;
        sq  += v[p].x * v[p].x + v[p].y * v[p].y + v[p].z * v[p].z + v[p].w * v[p].w;
    }
#pragma unroll
    for (int o = 16; o > 0; o >>= 1) {
        sum += __shfl_xor_sync(0xffffffffu, sum, o);
        sq  += __shfl_xor_sync(0xffffffffu, sq, o);
    }
    float mu   = sum * (1.f / 512.f);
    float var  = sq * (1.f / 512.f) - mu * mu;
    float rstd = rsqrtf(var + 1e-5f);

    __half* orow = g_XN1 + (size_t)t * DIMC;
#pragma unroll
    for (int p = 0; p < 4; p++) {
        int c = p * 128 + lane * 4;
        float4 g4 = *(const float4*)(gamma + c);
        float4 b4 = *(const float4*)(beta + c);
        __half2 h0 = __floats2half2_rn((v[p].x - mu) * rstd * g4.x + b4.x,
                                       (v[p].y - mu) * rstd * g4.y + b4.y);
        __half2 h1 = __floats2half2_rn((v[p].z - mu) * rstd * g4.z + b4.z,
                                       (v[p].w - mu) * rstd * g4.w + b4.w);
        uint2 u;
        u.x = *(uint32_t*)&h0;
        u.y = *(uint32_t*)&h1;
        *(uint2*)(orow + c) = u;
    }
}

// ---------------- LN2 (fp16 x1 input from g_XN1, image order) ---------------
__global__ void __launch_bounds__(256) ln2_kernel(const float* __restrict__ gamma,
                                                  const float* __restrict__ beta) {
    int t    = (blockIdx.x * 256 + threadIdx.x) >> 5;
    int lane = threadIdx.x & 31;

    const __half* row = g_XN1 + (size_t)t * DIMC;

    float v[16];
    float sum = 0.f, sq = 0.f;
#pragma unroll
    for (int p = 0; p < 4; p++) {
        uint2 u = *(const uint2*)(row + p * 128 + lane * 4);
        const __half2* hp = (const __half2*)&u;
        float2 f0 = __half22float2(hp[0]);
        float2 f1 = __half22float2(hp[1]);
        v[p * 4]     = f0.x; v[p * 4 + 1] = f0.y;
        v[p * 4 + 2] = f1.x; v[p * 4 + 3] = f1.y;
        sum += f0.x + f0.y + f1.x + f1.y;
        sq  += f0.x * f0.x + f0.y * f0.y + f1.x * f1.x + f1.y * f1.y;
    }
#pragma unroll
    for (int o = 16; o > 0; o >>= 1) {
        sum += __shfl_xor_sync(0xffffffffu, sum, o);
        sq  += __shfl_xor_sync(0xffffffffu, sq, o);
    }
    float mu   = sum * (1.f / 512.f);
    float var  = sq * (1.f / 512.f) - mu * mu;
    float rstd = rsqrtf(var + 1e-5f);

    __half* orow = g_XN2 + (size_t)t * DIMC;
#pragma unroll
    for (int p = 0; p < 4; p++) {
        int c = p * 128 + lane * 4;
        float4 g4 = *(const float4*)(gamma + c);
        float4 b4 = *(const float4*)(beta + c);
        __half2 h0 = __floats2half2_rn((v[p * 4]     - mu) * rstd * g4.x + b4.x,
                                       (v[p * 4 + 1] - mu) * rstd * g4.y + b4.y);
        __half2 h1 = __floats2half2_rn((v[p * 4 + 2] - mu) * rstd * g4.z + b4.z,
                                       (v[p * 4 + 3] - mu) * rstd * g4.w + b4.w);
        uint2 u;
        u.x = *(uint32_t*)&h0;
        u.y = *(uint32_t*)&h1;
        *(uint2*)(orow + c) = u;
    }
}

// ---------------- fp16 mma.sync GEMM: C[M,N] = A[M,K] @ W[N,K]^T ------------
// BM=128, BN=128, BK=64, 3-stage cp.async, XOR-8 swizzle, 8 warps of 64x32.
// ALL epilogues smem-staged for coalesced global traffic.
template <int NTOT, int KTOT, int OP>
__global__ void __launch_bounds__(256, 2) gemm_f16(const float* __restrict__ bias,
                                                   const float* __restrict__ aux,
                                                   float* __restrict__ outp) {
    constexpr int BM = 128, BN = 128, BK = 64, STAGES = 3;
    constexpr int KT = KTOT / BK;
    constexpr uint32_t AB    = BM * BK * 2;   // 16KB
    constexpr uint32_t BB    = BN * BK * 2;   // 16KB
    constexpr uint32_t STAGE = AB + BB;       // 32KB

    extern __shared__ char smem[];
    const uint32_t sbase = smem_u32(smem);
    const int tid = threadIdx.x;

    const __half* A;
    const __half* Bw;
    if (OP == 0)      { A = g_XN1; Bw = g_Wq; }
    else if (OP == 1) { A = g_O;   Bw = g_Wp; }
    else if (OP == 2) { A = g_XN2; Bw = g_W1; }
    else              { A = g_H1;  Bw = g_W2; }

    const int m0 = blockIdx.y * BM;
    const int n0 = blockIdx.x * BN;

    auto load_tile = [&](int kt, int s) {
        const __half* gA = A + (size_t)m0 * KTOT + kt * BK;
        const __half* gB = Bw + (size_t)n0 * KTOT + kt * BK;
#pragma unroll
        for (int i = 0; i < 4; i++) {
            int idx = i * 256 + tid;
            int r = idx >> 3, g = idx & 7;
            uint32_t off = (uint32_t)(r * 128 + ((g ^ (r & 7)) << 4));
            uint32_t da = sbase + (uint32_t)s * STAGE + off;
            const __half* pa = gA + (size_t)r * KTOT + g * 8;
            asm volatile("cp.async.cg.shared.global [%0], [%1], 16;\n" ::"r"(da), "l"(pa));
            uint32_t db = sbase + (uint32_t)s * STAGE + AB + off;
            const __half* pb = gB + (size_t)r * KTOT + g * 8;
            asm volatile("cp.async.cg.shared.global [%0], [%1], 16;\n" ::"r"(db), "l"(pb));
        }
        asm volatile("cp.async.commit_group;\n");
    };

    const int w    = tid >> 5;
    const int wm   = w >> 2;
    const int wn   = w & 3;
    const int lane = tid & 31;
    const int grp  = lane >> 2;
    const int tig  = lane & 3;

    float acc[4][4][4];
#pragma unroll
    for (int i = 0; i < 4; i++)
#pragma unroll
        for (int j = 0; j < 4; j++)
#pragma unroll
            for (int r = 0; r < 4; r++) acc[i][j][r] = 0.f;

    const int a_row  = wm * 64 + (lane & 15);
    const int a_chk0 = lane >> 4;
    const int b_row  = wn * 32 + (lane & 7) + ((lane >> 4) << 3);
    const int b_chk0 = (lane >> 3) & 1;

    load_tile(0, 0);
    load_tile(1, 1);

#pragma unroll 1
    for (int kt = 0; kt < KT; ++kt) {
        if (kt + 2 < KT) asm volatile("cp.async.wait_group 1;\n");
        else             asm volatile("cp.async.wait_group 0;\n");
        __syncthreads();

        if (kt + 2 < KT) load_tile(kt + 2, (kt + 2) % STAGES);

        const uint32_t stA = sbase + (uint32_t)(kt % STAGES) * STAGE;
        const uint32_t stB = stA + AB;

#pragma unroll
        for (int ks = 0; ks < 4; ++ks) {
            uint32_t a[4][4], b[2][4];
#pragma unroll
            for (int mt = 0; mt < 4; ++mt) {
                int r = a_row + mt * 16;
                int c = ks * 2 + a_chk0;
                uint32_t ad = stA + (uint32_t)(r * 128 + ((c ^ (r & 7)) << 4));
                LDSM_X4(a[mt][0], a[mt][1], a[mt][2], a[mt][3], ad);
            }
#pragma unroll
            for (int nt2 = 0; nt2 < 2; ++nt2) {
                int r = b_row + nt2 * 16;
                int c = ks * 2 + b_chk0;
                uint32_t bd = stB + (uint32_t)(r * 128 + ((c ^ (r & 7)) << 4));
                LDSM_X4(b[nt2][0], b[nt2][1], b[nt2][2], b[nt2][3], bd);
            }
#pragma unroll
            for (int mt = 0; mt < 4; ++mt)
#pragma unroll
                for (int nt = 0; nt < 4; ++nt)
                    MMA16816(acc[mt][nt], a[mt], b[nt >> 1][(nt & 1) * 2], b[nt >> 1][(nt & 1) * 2 + 1]);
        }
    }

    // ---- epilogue (all paths smem-staged) ----
    if (OP == 3) {
        constexpr int OSTRF = 132;   // floats per row (528B)
        float* sOutF = (float*)smem;
        __syncthreads();
#pragma unroll
        for (int mt = 0; mt < 4; ++mt) {
            int row_lo = wm * 64 + mt * 16 + grp;
#pragma unroll
            for (int nt = 0; nt < 4; ++nt) {
                int col = wn * 32 + nt * 8 + 2 * tig;
                float b0 = bias[n0 + col], b1 = bias[n0 + col + 1];
                *(float2*)(sOutF + row_lo * OSTRF + col) =
                    make_float2(acc[mt][nt][0] + b0, acc[mt][nt][1] + b1);
                *(float2*)(sOutF + (row_lo + 8) * OSTRF + col) =
                    make_float2(acc[mt][nt][2] + b0, acc[mt][nt][3] + b1);
            }
        }
        __syncthreads();
#pragma unroll
        for (int i = 0; i < 16; i++) {
            int id  = i * 256 + tid;
            int row = id >> 5, c4 = id & 31;
            int col = c4 * 4;
            float4 v = *(const float4*)(sOutF + row * OSTRF + col);
            size_t o = (size_t)(m0 + row) * NTOT + n0 + col;
            uint2 u = *(const uint2*)(g_XN1 + o);
            const __half2* hp = (const __half2*)&u;
            float2 x0 = __half22float2(hp[0]);
            float2 x1 = __half22float2(hp[1]);
            v.x += x0.x; v.y += x0.y; v.z += x1.x; v.w += x1.y;
            *(float4*)(outp + o) = v;
        }
    } else {
        constexpr int OSTR = 136;
        __half* sOut = (__half*)smem;
        __syncthreads();
#pragma unroll
        for (int mt = 0; mt < 4; ++mt) {
            int row_lo = wm * 64 + mt * 16 + grp;
#pragma unroll
            for (int nt = 0; nt < 4; ++nt) {
                int col = wn * 32 + nt * 8 + 2 * tig;
                float b0 = bias[n0 + col], b1 = bias[n0 + col + 1];
                float v00 = acc[mt][nt][0] + b0;
                float v01 = acc[mt][nt][1] + b1;
                float v10 = acc[mt][nt][2] + b0;
                float v11 = acc[mt][nt][3] + b1;
                if (OP == 2) {
                    v00 = gelu_f(v00); v01 = gelu_f(v01);
                    v10 = gelu_f(v10); v11 = gelu_f(v11);
                }
                *(__half2*)(sOut + row_lo * OSTR + col)       = __floats2half2_rn(v00, v01);
                *(__half2*)(sOut + (row_lo + 8) * OSTR + col) = __floats2half2_rn(v10, v11);
            }
        }
        __syncthreads();
        if (OP == 1) {
#pragma unroll
            for (int i = 0; i < 8; i++) {
                int id  = i * 256 + tid;
                int row = id >> 4, c16 = id & 15;
                size_t dimg = win_to_img(m0 + row) * DIMC + n0 + c16 * 8;
                uint4 v = *(const uint4*)(sOut + row * OSTR + c16 * 8);
                const __half2* hv = (const __half2*)&v;
                float4 a0 = *(const float4*)(aux + dimg);
                float4 a1 = *(const float4*)(aux + dimg + 4);
                float2 f0 = __half22float2(hv[0]);
                float2 f1 = __half22float2(hv[1]);
                float2 f2 = __half22float2(hv[2]);
                float2 f3 = __half22float2(hv[3]);
                uint4 o;
                o.x = h2bits(a0.x + f0.x, a0.y + f0.y);
                o.y = h2bits(a0.z + f1.x, a0.w + f1.y);
                o.z = h2bits(a1.x + f2.x, a1.y + f2.y);
                o.w = h2bits(a1.z + f3.x, a1.w + f3.y);
                *(uint4*)(g_XN1 + dimg) = o;
            }
        } else {
            __half* dst = (OP == 0) ? g_QKV : g_H1;
#pragma unroll
            for (int i = 0; i < 8; i++) {
                int id  = i * 256 + tid;
                int row = id >> 4, c16 = id & 15;
                uint4 v = *(const uint4*)(sOut + row * OSTR + c16 * 8);
                *(uint4*)(dst + (size_t)(m0 + row) * NTOT + n0 + c16 * 8) = v;
            }
        }
    }
}

// ---------------- attention via mma.sync: one 256-thread block per (win, head-pair)
// Warps 0-3 process head 2*hp, warps 4-7 head 2*hp+1. Q/K/V rows are 128B
// (two heads' 64B slices) -> fully coalesced global loads, natural SW128 rows.
__global__ void __launch_bounds__(256) attn_kernel() {
    __shared__ __align__(16) __half sQKV[3 * 64 * 64];  // Q,K,V: 8KB each
    __shared__ __align__(16) __half sO[64 * 72];        // staging (stride 72)
    __shared__ float srpb[450];
    __shared__ int   slab[64];

    const int bh   = blockIdx.x;
    const int b_   = bh >> 3;
    const int hp   = bh & 7;        // head pair
    const int tid  = threadIdx.x;
    const int w    = tid >> 5;      // 0..7
    const int hl   = w >> 2;        // head within pair
    const int wq   = w & 3;         // row quarter
    const int lane = tid & 31;
    const int grp  = lane >> 2;
    const int tig  = lane & 3;

    const uint32_t qb = smem_u32(sQKV);
    const uint32_t kb = qb + 8192;
    const uint32_t vb = qb + 16384;

    // 128B rows, XOR-8 swizzle: row r (0..63), chunk g (0..7 of 16B)
    auto off8 = [](int r, int g) -> uint32_t {
        return (uint32_t)(r * 128 + ((g ^ (r & 7)) << 4));
    };

    // ---- load Q,K,V: 1536 16B chunks / 256 threads = 6 iters, coalesced ----
    const __half* base = g_QKV + (size_t)(b_ * 64) * (3 * DIMC) + hp * 64;
#pragma unroll
    for (int i = 0; i < 6; i++) {
        int idx = i * 256 + tid;          // 0..1535
        int tz  = idx >> 9;               // 0=Q,1=K,2=V
        int rem = idx & 511;
        int r = rem >> 3, g = rem & 7;
        const __half* src = base + (size_t)r * (3 * DIMC) + tz * DIMC + g * 8;
        *(uint4*)((char*)sQKV + tz * 8192 + off8(r, g)) = *(const uint4*)src;
    }
    if (tid < 64) {
        int widx = b_ & 63;
        int gh = ((widx >> 3) << 3) + (tid >> 3);
        int gw = ((widx & 7) << 3) + (tid & 7);
        int zh = gh < 56 ? 0 : (gh < 60 ? 1 : 2);
        int zw = gw < 56 ? 0 : (gw < 60 ? 1 : 2);
        slab[tid] = zh * 3 + zw;
    }
    for (int i = tid; i < 450; i += 256) {
        int hh = i >= 225;
        srpb[i] = g_RPBt[(hp * 2 + hh) * 225 + (i - hh * 225)];
    }
    __syncthreads();

    // ---- S = Q @ K^T (per head): warp computes 16 q-rows x 64 keys ----
    float s[8][4];
#pragma unroll
    for (int i = 0; i < 8; i++)
#pragma unroll
        for (int j = 0; j < 4; j++) s[i][j] = 0.f;

    const int hc     = hl * 4;                 // chunk base for this head
    const int a_row  = wq * 16 + (lane & 15);
    const int a_chk0 = lane >> 4;
    const int b_row  = (lane & 7) + ((lane >> 4) << 3);
    const int b_chk0 = (lane >> 3) & 1;

#pragma unroll
    for (int ks = 0; ks < 2; ++ks) {
        uint32_t a[4], b[4][4];
        LDSM_X4(a[0], a[1], a[2], a[3], qb + off8(a_row, hc + ks * 2 + a_chk0));
#pragma unroll
        for (int nt2 = 0; nt2 < 4; ++nt2)
            LDSM_X4(b[nt2][0], b[nt2][1], b[nt2][2], b[nt2][3],
                    kb + off8(nt2 * 16 + b_row, hc + ks * 2 + b_chk0));
#pragma unroll
        for (int nt = 0; nt < 8; ++nt)
            MMA16816(s[nt], a, b[nt >> 1][(nt & 1) * 2], b[nt >> 1][(nt & 1) * 2 + 1]);
    }

    // ---- bias + mask + exp; row sums ----
    const float scale = 0.17677669529663687f;
    const int r0 = wq * 16 + grp;
    const int r1 = r0 + 8;
    const int rh0 = r0 >> 3, rw0 = r0 & 7;
    const int rh1 = r1 >> 3;
    const int lab0 = slab[r0], lab1 = slab[r1];
    const float* rp = srpb + hl * 225;

    float sum0 = 0.f, sum1 = 0.f;
#pragma unroll
    for (int nt = 0; nt < 8; ++nt) {
#pragma unroll
        for (int e = 0; e < 2; ++e) {
            int c  = nt * 8 + tig * 2 + e;
            int mh = c >> 3, mw = c & 7;
            int lb = slab[c];
            float bi0 = rp[(rh0 - mh + 7) * 15 + (rw0 - mw + 7)];
            float bi1 = rp[(rh1 - mh + 7) * 15 + (rw0 - mw + 7)];
            float v0 = s[nt][e]     * scale + bi0 + (lab0 == lb ? 0.f : -100.f);
            float v1 = s[nt][2 + e] * scale + bi1 + (lab1 == lb ? 0.f : -100.f);
            float e0 = __expf(v0);
            float e1 = __expf(v1);
            s[nt][e]     = e0;
            s[nt][2 + e] = e1;
            sum0 += e0;
            sum1 += e1;
        }
    }
    sum0 += __shfl_xor_sync(0xffffffffu, sum0, 1);
    sum0 += __shfl_xor_sync(0xffffffffu, sum0, 2);
    sum1 += __shfl_xor_sync(0xffffffffu, sum1, 1);
    sum1 += __shfl_xor_sync(0xffffffffu, sum1, 2);

    // ---- O = P @ V (per head) ----
    float o[4][4];
#pragma unroll
    for (int i = 0; i < 4; i++)
#pragma unroll
        for (int j = 0; j < 4; j++) o[i][j] = 0.f;

#pragma unroll
    for (int ks2 = 0; ks2 < 4; ++ks2) {
        uint32_t pa[4];
        pa[0] = h2bits(s[ks2 * 2][0],     s[ks2 * 2][1]);
        pa[1] = h2bits(s[ks2 * 2][2],     s[ks2 * 2][3]);
        pa[2] = h2bits(s[ks2 * 2 + 1][0], s[ks2 * 2 + 1][1]);
        pa[3] = h2bits(s[ks2 * 2 + 1][2], s[ks2 * 2 + 1][3]);
        int vrow = ks2 * 16 + (lane & 15);
        uint32_t bv0[4], bv1[4];
        LDSM_X4_T(bv0[0], bv0[1], bv0[2], bv0[3], vb + off8(vrow, hc + (lane >> 4)));
        LDSM_X4_T(bv1[0], bv1[1], bv1[2], bv1[3], vb + off8(vrow, hc + 2 + (lane >> 4)));
        MMA16816(o[0], pa, bv0[0], bv0[1]);
        MMA16816(o[1], pa, bv0[2], bv0[3]);
        MMA16816(o[2], pa, bv1[0], bv1[1]);
        MMA16816(o[3], pa, bv1[2], bv1[3]);
    }

    // ---- stage O (both heads) in smem, then coalesced 128B row stores ----
    const float inv0 = 1.f / sum0;
    const float inv1 = 1.f / sum1;
#pragma unroll
    for (int nt = 0; nt < 4; ++nt) {
        int d = hl * 32 + nt * 8 + tig * 2;
        *(__half2*)(sO + r0 * 72 + d) = __floats2half2_rn(o[nt][0] * inv0, o[nt][1] * inv0);
        *(__half2*)(sO + r1 * 72 + d) = __floats2half2_rn(o[nt][2] * inv1, o[nt][3] * inv1);
    }
    __syncthreads();
    __half* obase = g_O + (size_t)(b_ * 64) * DIMC + hp * 64;
#pragma unroll
    for (int i = 0; i < 2; i++) {
        int idx = i * 256 + tid;            // 512 chunks of 16B
        int r = idx >> 3, ch = idx & 7;
        uint4 v = *(const uint4*)(sO + r * 72 + ch * 8);
        *(uint4*)(obase + (size_t)r * DIMC + ch * 8) = v;
    }
}

// ---------------- host launcher ----------------
extern "C" void kernel_launch(void* const* d_in, const int* in_sizes, int n_in,
                              void* d_out, int out_size) {
    const float* x      = (const float*)d_in[0];
    const float* n1g    = (const float*)d_in[1];
    const float* n1b    = (const float*)d_in[2];
    const float* qkv_w  = (const float*)d_in[3];
    const float* qkv_b  = (const float*)d_in[4];
    const float* proj_w = (const float*)d_in[5];
    const float* proj_b = (const float*)d_in[6];
    const float* rpb    = (const float*)d_in[7];
    const float* n2g    = (const float*)d_in[8];
    const float* n2b    = (const float*)d_in[9];
    const float* fc1_w  = (const float*)d_in[10];
    const float* fc1_b  = (const float*)d_in[11];
    const float* fc2_w  = (const float*)d_in[12];
    const float* fc2_b  = (const float*)d_in[13];
    float* out = (float*)d_out;

    constexpr int SMEMB = 3 * (128 * 64 * 2 + 128 * 64 * 2);  // 98304 bytes

    cudaFuncSetAttribute(gemm_f16<1536, 512, 0>, cudaFuncAttributeMaxDynamicSharedMemorySize, SMEMB);
    cudaFuncSetAttribute(gemm_f16<512,  512, 1>, cudaFuncAttributeMaxDynamicSharedMemorySize, SMEMB);
    cudaFuncSetAttribute(gemm_f16<2048, 512, 2>, cudaFuncAttributeMaxDynamicSharedMemorySize, SMEMB);
    cudaFuncSetAttribute(gemm_f16<512, 2048, 3>, cudaFuncAttributeMaxDynamicSharedMemorySize, SMEMB);

    // weights -> fp16 copies + rpb transpose (single kernel)
    cvt_all<<<(NW1 + 255) / 256, 256>>>(qkv_w, proj_w, fc1_w, fc2_w, rpb);

    // LN1 + shift + window partition -> g_XN1 (window order)
    ln1_kernel<<<MROWS / 8, 256>>>(x, n1g, n1b);

    // QKV projection
    gemm_f16<1536, 512, 0><<<dim3(1536 / 128, MROWS / 128), 256, SMEMB>>>(qkv_b, nullptr, nullptr);

    // windowed attention (tensor-core, 2 heads per block)
    attn_kernel<<<BWIN * 8, 256>>>();

    // output projection + window reverse + shift + residual -> g_XN1 (x1, fp16)
    gemm_f16<512, 512, 1><<<dim3(512 / 128, MROWS / 128), 256, SMEMB>>>(proj_b, x, nullptr);

    // LN2 (reads fp16 x1)
    ln2_kernel<<<MROWS / 8, 256>>>(n2g, n2b);

    // FC1 + gelu (fast tanh-form)
    gemm_f16<2048, 512, 2><<<dim3(2048 / 128, MROWS / 128), 256, SMEMB>>>(fc1_b, nullptr, nullptr);

    // FC2 + residual: out = x1 + acc + bias (write-only fp32)
    gemm_f16<512, 2048, 3><<<dim3(512 / 128, MROWS / 128), 256, SMEMB>>>(fc2_b, nullptr, out);
}

// round 16
// speedup vs baseline: 1.0385x; 1.0025x over previous
#include <cuda_runtime.h>
#include <cuda_fp16.h>
#include <cstdint>

// ---------------- problem constants ----------------
#define DIMC   512
#define NHEADS 16
#define SSZ    4
#define BWIN   2048          // 32 batches * 64 windows
#define MROWS  131072        // BWIN * 64 == B*L
#define CHID   2048          // mlp hidden

// ---------------- scratch (device globals; no allocs allowed) ----------------
__device__ __half g_XN1[(size_t)MROWS * DIMC];
__device__ __half g_QKV[(size_t)MROWS * 3 * DIMC];
__device__ __half g_O  [(size_t)MROWS * DIMC];
__device__ __half g_XN2[(size_t)MROWS * DIMC];
__device__ __half g_H1 [(size_t)MROWS * CHID];
__device__ __half g_Wq [3 * DIMC * DIMC];
__device__ __half g_Wp [DIMC * DIMC];
__device__ __half g_W1 [CHID * DIMC];
__device__ __half g_W2 [DIMC * CHID];
__device__ float  g_RPBt[NHEADS * 225];   // transposed rel-pos bias

#define NWQ (3 * DIMC * DIMC)
#define NWP (DIMC * DIMC)
#define NW1 (CHID * DIMC)
#define NW2 (DIMC * CHID)

// ---------------- helpers ----------------
// fast GELU: tanh form via sigmoid; |err| < 1e-4 over the FC1 activation range
__device__ __forceinline__ float gelu_f(float x) {
    float t = x * (0.7978845608f + 0.0356774081f * x * x);
    return x * __frcp_rn(1.f + __expf(-2.f * t));
}

__device__ __forceinline__ uint32_t smem_u32(const void* p) {
    return (uint32_t)__cvta_generic_to_shared(p);
}

// token index in window order -> token index in (B,H,W) order (shift mapping)
__device__ __forceinline__ size_t win_to_img(int t) {
    int b_   = t >> 6, nn = t & 63;
    int bimg = b_ >> 6, widx = b_ & 63;
    int gh = ((widx >> 3) << 3) + (nn >> 3);
    int gw = ((widx & 7) << 3) + (nn & 7);
    int sh = (gh + SSZ) & 63;
    int sw = (gw + SSZ) & 63;
    return ((size_t)bimg << 12) + (size_t)(sh << 6) + (size_t)sw;
}

#define LDSM_X4(r0, r1, r2, r3, addr)                                          \
    asm volatile("ldmatrix.sync.aligned.m8n8.x4.shared.b16 {%0,%1,%2,%3}, [%4];" \
                 : "=r"(r0), "=r"(r1), "=r"(r2), "=r"(r3) : "r"(addr))

#define LDSM_X4_T(r0, r1, r2, r3, addr)                                        \
    asm volatile("ldmatrix.sync.aligned.m8n8.x4.trans.shared.b16 {%0,%1,%2,%3}, [%4];" \
                 : "=r"(r0), "=r"(r1), "=r"(r2), "=r"(r3) : "r"(addr))

#define MMA16816(d, a, b0, b1)                                                 \
    asm volatile(                                                              \
        "mma.sync.aligned.m16n8k16.row.col.f32.f16.f16.f32 "                   \
        "{%0,%1,%2,%3},{%4,%5,%6,%7},{%8,%9},{%0,%1,%2,%3};"                   \
        : "+f"((d)[0]), "+f"((d)[1]), "+f"((d)[2]), "+f"((d)[3])               \
        : "r"((a)[0]), "r"((a)[1]), "r"((a)[2]), "r"((a)[3]),                  \
          "r"(b0), "r"(b1))

__device__ __forceinline__ uint32_t h2bits(float x, float y) {
    __half2 h = __floats2half2_rn(x, y);
    return *(uint32_t*)&h;
}

// ---------------- LN1 (fp32 input, shift+window remap) + weight cvt ---------
// Weight conversion + rpb transpose folded in as independent side-work
// (grid 16384x256 covers all 4.2M weight elements).
__global__ void __launch_bounds__(256) ln1_kernel(const float* __restrict__ xin,
                                                  const float* __restrict__ gamma,
                                                  const float* __restrict__ beta,
                                                  const float* __restrict__ wq,
                                                  const float* __restrict__ wp,
                                                  const float* __restrict__ w1,
                                                  const float* __restrict__ w2,
                                                  const float* __restrict__ rpb) {
    // ---- side work: weight conversion ----
    int gid = blockIdx.x * 256 + threadIdx.x;
    if (gid < NWQ) g_Wq[gid] = __float2half(wq[gid]);
    if (gid < NWP) g_Wp[gid] = __float2half(wp[gid]);
    if (gid < NW1) g_W1[gid] = __float2half(w1[gid]);
    if (gid < NW2) g_W2[gid] = __float2half(w2[gid]);
    if (gid < NHEADS * 225) {
        int h = gid / 225, j = gid % 225;
        g_RPBt[gid] = rpb[j * NHEADS + h];
    }

    // ---- LN1 ----
    int t    = gid >> 5;
    int lane = threadIdx.x & 31;

    size_t src = win_to_img(t);
    const float* row = xin + src * DIMC;

    float4 v[4];
    float sum = 0.f, sq = 0.f;
#pragma unroll
    for (int p = 0; p < 4; p++) {
        v[p] = *(const float4*)(row + p * 128 + lane * 4);
        sum += v[p].x + v[p].y + v[p].z + v[p].w;
        sq  += v[p].x * v[p].x + v[p].y * v[p].y + v[p].z * v[p].z + v[p].w * v[p].w;
    }
#pragma unroll
    for (int o = 16; o > 0; o >>= 1) {
        sum += __shfl_xor_sync(0xffffffffu, sum, o);
        sq  += __shfl_xor_sync(0xffffffffu, sq, o);
    }
    float mu   = sum * (1.f / 512.f);
    float var  = sq * (1.f / 512.f) - mu * mu;
    float rstd = rsqrtf(var + 1e-5f);

    __half* orow = g_XN1 + (size_t)t * DIMC;
#pragma unroll
    for (int p = 0; p < 4; p++) {
        int c = p * 128 + lane * 4;
        float4 g4 = *(const float4*)(gamma + c);
        float4 b4 = *(const float4*)(beta + c);
        __half2 h0 = __floats2half2_rn((v[p].x - mu) * rstd * g4.x + b4.x,
                                       (v[p].y - mu) * rstd * g4.y + b4.y);
        __half2 h1 = __floats2half2_rn((v[p].z - mu) * rstd * g4.z + b4.z,
                                       (v[p].w - mu) * rstd * g4.w + b4.w);
        uint2 u;
        u.x = *(uint32_t*)&h0;
        u.y = *(uint32_t*)&h1;
        *(uint2*)(orow + c) = u;
    }
}

// ---------------- LN2 (fp16 x1 input from g_XN1, image order) ---------------
__global__ void __launch_bounds__(256) ln2_kernel(const float* __restrict__ gamma,
                                                  const float* __restrict__ beta) {
    int t    = (blockIdx.x * 256 + threadIdx.x) >> 5;
    int lane = threadIdx.x & 31;

    const __half* row = g_XN1 + (size_t)t * DIMC;

    float v[16];
    float sum = 0.f, sq = 0.f;
#pragma unroll
    for (int p = 0; p < 4; p++) {
        uint2 u = *(const uint2*)(row + p * 128 + lane * 4);
        const __half2* hp = (const __half2*)&u;
        float2 f0 = __half22float2(hp[0]);
        float2 f1 = __half22float2(hp[1]);
        v[p * 4]     = f0.x; v[p * 4 + 1] = f0.y;
        v[p * 4 + 2] = f1.x; v[p * 4 + 3] = f1.y;
        sum += f0.x + f0.y + f1.x + f1.y;
        sq  += f0.x * f0.x + f0.y * f0.y + f1.x * f1.x + f1.y * f1.y;
    }
#pragma unroll
    for (int o = 16; o > 0; o >>= 1) {
        sum += __shfl_xor_sync(0xffffffffu, sum, o);
        sq  += __shfl_xor_sync(0xffffffffu, sq, o);
    }
    float mu   = sum * (1.f / 512.f);
    float var  = sq * (1.f / 512.f) - mu * mu;
    float rstd = rsqrtf(var + 1e-5f);

    __half* orow = g_XN2 + (size_t)t * DIMC;
#pragma unroll
    for (int p = 0; p < 4; p++) {
        int c = p * 128 + lane * 4;
        float4 g4 = *(const float4*)(gamma + c);
        float4 b4 = *(const float4*)(beta + c);
        __half2 h0 = __floats2half2_rn((v[p * 4]     - mu) * rstd * g4.x + b4.x,
                                       (v[p * 4 + 1] - mu) * rstd * g4.y + b4.y);
        __half2 h1 = __floats2half2_rn((v[p * 4 + 2] - mu) * rstd * g4.z + b4.z,
                                       (v[p * 4 + 3] - mu) * rstd * g4.w + b4.w);
        uint2 u;
        u.x = *(uint32_t*)&h0;
        u.y = *(uint32_t*)&h1;
        *(uint2*)(orow + c) = u;
    }
}

// ---------------- fp16 mma.sync GEMM: C[M,N] = A[M,K] @ W[N,K]^T ------------
// BM=128, BN=128, BK=64, 3-stage cp.async, XOR-8 swizzle, 8 warps of 64x32.
// ALL epilogues smem-staged for coalesced global traffic.
template <int NTOT, int KTOT, int OP>
__global__ void __launch_bounds__(256, 2) gemm_f16(const float* __restrict__ bias,
                                                   const float* __restrict__ aux,
                                                   float* __restrict__ outp) {
    constexpr int BM = 128, BN = 128, BK = 64, STAGES = 3;
    constexpr int KT = KTOT / BK;
    constexpr uint32_t AB    = BM * BK * 2;   // 16KB
    constexpr uint32_t BB    = BN * BK * 2;   // 16KB
    constexpr uint32_t STAGE = AB + BB;       // 32KB

    extern __shared__ char smem[];
    const uint32_t sbase = smem_u32(smem);
    const int tid = threadIdx.x;

    const __half* A;
    const __half* Bw;
    if (OP == 0)      { A = g_XN1; Bw = g_Wq; }
    else if (OP == 1) { A = g_O;   Bw = g_Wp; }
    else if (OP == 2) { A = g_XN2; Bw = g_W1; }
    else              { A = g_H1;  Bw = g_W2; }

    const int m0 = blockIdx.y * BM;
    const int n0 = blockIdx.x * BN;

    auto load_tile = [&](int kt, int s) {
        const __half* gA = A + (size_t)m0 * KTOT + kt * BK;
        const __half* gB = Bw + (size_t)n0 * KTOT + kt * BK;
#pragma unroll
        for (int i = 0; i < 4; i++) {
            int idx = i * 256 + tid;
            int r = idx >> 3, g = idx & 7;
            uint32_t off = (uint32_t)(r * 128 + ((g ^ (r & 7)) << 4));
            uint32_t da = sbase + (uint32_t)s * STAGE + off;
            const __half* pa = gA + (size_t)r * KTOT + g * 8;
            asm volatile("cp.async.cg.shared.global [%0], [%1], 16;\n" ::"r"(da), "l"(pa));
            uint32_t db = sbase + (uint32_t)s * STAGE + AB + off;
            const __half* pb = gB + (size_t)r * KTOT + g * 8;
            asm volatile("cp.async.cg.shared.global [%0], [%1], 16;\n" ::"r"(db), "l"(pb));
        }
        asm volatile("cp.async.commit_group;\n");
    };

    const int w    = tid >> 5;
    const int wm   = w >> 2;
    const int wn   = w & 3;
    const int lane = tid & 31;
    const int grp  = lane >> 2;
    const int tig  = lane & 3;

    float acc[4][4][4];
#pragma unroll
    for (int i = 0; i < 4; i++)
#pragma unroll
        for (int j = 0; j < 4; j++)
#pragma unroll
            for (int r = 0; r < 4; r++) acc[i][j][r] = 0.f;

    const int a_row  = wm * 64 + (lane & 15);
    const int a_chk0 = lane >> 4;
    const int b_row  = wn * 32 + (lane & 7) + ((lane >> 4) << 3);
    const int b_chk0 = (lane >> 3) & 1;

    load_tile(0, 0);
    load_tile(1, 1);

#pragma unroll 1
    for (int kt = 0; kt < KT; ++kt) {
        if (kt + 2 < KT) asm volatile("cp.async.wait_group 1;\n");
        else             asm volatile("cp.async.wait_group 0;\n");
        __syncthreads();

        if (kt + 2 < KT) load_tile(kt + 2, (kt + 2) % STAGES);

        const uint32_t stA = sbase + (uint32_t)(kt % STAGES) * STAGE;
        const uint32_t stB = stA + AB;

#pragma unroll
        for (int ks = 0; ks < 4; ++ks) {
            uint32_t a[4][4], b[2][4];
#pragma unroll
            for (int mt = 0; mt < 4; ++mt) {
                int r = a_row + mt * 16;
                int c = ks * 2 + a_chk0;
                uint32_t ad = stA + (uint32_t)(r * 128 + ((c ^ (r & 7)) << 4));
                LDSM_X4(a[mt][0], a[mt][1], a[mt][2], a[mt][3], ad);
            }
#pragma unroll
            for (int nt2 = 0; nt2 < 2; ++nt2) {
                int r = b_row + nt2 * 16;
                int c = ks * 2 + b_chk0;
                uint32_t bd = stB + (uint32_t)(r * 128 + ((c ^ (r & 7)) << 4));
                LDSM_X4(b[nt2][0], b[nt2][1], b[nt2][2], b[nt2][3], bd);
            }
#pragma unroll
            for (int mt = 0; mt < 4; ++mt)
#pragma unroll
                for (int nt = 0; nt < 4; ++nt)
                    MMA16816(acc[mt][nt], a[mt], b[nt >> 1][(nt & 1) * 2], b[nt >> 1][(nt & 1) * 2 + 1]);
        }
    }

    // ---- epilogue (all paths smem-staged) ----
    if (OP == 3) {
        constexpr int OSTRF = 132;   // floats per row (528B)
        float* sOutF = (float*)smem;
        __syncthreads();
#pragma unroll
        for (int mt = 0; mt < 4; ++mt) {
            int row_lo = wm * 64 + mt * 16 + grp;
#pragma unroll
            for (int nt = 0; nt < 4; ++nt) {
                int col = wn * 32 + nt * 8 + 2 * tig;
                float b0 = bias[n0 + col], b1 = bias[n0 + col + 1];
                *(float2*)(sOutF + row_lo * OSTRF + col) =
                    make_float2(acc[mt][nt][0] + b0, acc[mt][nt][1] + b1);
                *(float2*)(sOutF + (row_lo + 8) * OSTRF + col) =
                    make_float2(acc[mt][nt][2] + b0, acc[mt][nt][3] + b1);
            }
        }
        __syncthreads();
#pragma unroll
        for (int i = 0; i < 16; i++) {
            int id  = i * 256 + tid;
            int row = id >> 5, c4 = id & 31;
            int col = c4 * 4;
            float4 v = *(const float4*)(sOutF + row * OSTRF + col);
            size_t o = (size_t)(m0 + row) * NTOT + n0 + col;
            uint2 u = *(const uint2*)(g_XN1 + o);
            const __half2* hp = (const __half2*)&u;
            float2 x0 = __half22float2(hp[0]);
            float2 x1 = __half22float2(hp[1]);
            v.x += x0.x; v.y += x0.y; v.z += x1.x; v.w += x1.y;
            *(float4*)(outp + o) = v;
        }
    } else {
        constexpr int OSTR = 136;
        __half* sOut = (__half*)smem;
        __syncthreads();
#pragma unroll
        for (int mt = 0; mt < 4; ++mt) {
            int row_lo = wm * 64 + mt * 16 + grp;
#pragma unroll
            for (int nt = 0; nt < 4; ++nt) {
                int col = wn * 32 + nt * 8 + 2 * tig;
                float b0 = bias[n0 + col], b1 = bias[n0 + col + 1];
                float v00 = acc[mt][nt][0] + b0;
                float v01 = acc[mt][nt][1] + b1;
                float v10 = acc[mt][nt][2] + b0;
                float v11 = acc[mt][nt][3] + b1;
                if (OP == 2) {
                    v00 = gelu_f(v00); v01 = gelu_f(v01);
                    v10 = gelu_f(v10); v11 = gelu_f(v11);
                }
                *(__half2*)(sOut + row_lo * OSTR + col)       = __floats2half2_rn(v00, v01);
                *(__half2*)(sOut + (row_lo + 8) * OSTR + col) = __floats2half2_rn(v10, v11);
            }
        }
        __syncthreads();
        if (OP == 1) {
#pragma unroll
            for (int i = 0; i < 8; i++) {
                int id  = i * 256 + tid;
                int row = id >> 4, c16 = id & 15;
                size_t dimg = win_to_img(m0 + row) * DIMC + n0 + c16 * 8;
                uint4 v = *(const uint4*)(sOut + row * OSTR + c16 * 8);
                const __half2* hv = (const __half2*)&v;
                float4 a0 = *(const float4*)(aux + dimg);
                float4 a1 = *(const float4*)(aux + dimg + 4);
                float2 f0 = __half22float2(hv[0]);
                float2 f1 = __half22float2(hv[1]);
                float2 f2 = __half22float2(hv[2]);
                float2 f3 = __half22float2(hv[3]);
                uint4 o;
                o.x = h2bits(a0.x + f0.x, a0.y + f0.y);
                o.y = h2bits(a0.z + f1.x, a0.w + f1.y);
                o.z = h2bits(a1.x + f2.x, a1.y + f2.y);
                o.w = h2bits(a1.z + f3.x, a1.w + f3.y);
                *(uint4*)(g_XN1 + dimg) = o;
            }
        } else {
            __half* dst = (OP == 0) ? g_QKV : g_H1;
#pragma unroll
            for (int i = 0; i < 8; i++) {
                int id  = i * 256 + tid;
                int row = id >> 4, c16 = id & 15;
                uint4 v = *(const uint4*)(sOut + row * OSTR + c16 * 8);
                *(uint4*)(dst + (size_t)(m0 + row) * NTOT + n0 + c16 * 8) = v;
            }
        }
    }
}

// ---------------- attention via mma.sync: one 256-thread block per (win, head-pair)
// Warps 0-3 process head 2*hp, warps 4-7 head 2*hp+1. Q/K/V rows are 128B
// (two heads' 64B slices) -> fully coalesced global loads, natural SW128 rows.
// Mask zones factored (slabh[8]/slabw[8]); bias indices affine in nt.
__global__ void __launch_bounds__(256) attn_kernel() {
    __shared__ __align__(16) __half sQKV[3 * 64 * 64];  // Q,K,V: 8KB each
    __shared__ __align__(16) __half sO[64 * 72];        // staging (stride 72)
    __shared__ float srpb[450];
    __shared__ int   slabh[8];
    __shared__ int   slabw[8];

    const int bh   = blockIdx.x;
    const int b_   = bh >> 3;
    const int hp   = bh & 7;        // head pair
    const int tid  = threadIdx.x;
    const int w    = tid >> 5;      // 0..7
    const int hl   = w >> 2;        // head within pair
    const int wq   = w & 3;         // row quarter
    const int lane = tid & 31;
    const int grp  = lane >> 2;
    const int tig  = lane & 3;

    const uint32_t qb = smem_u32(sQKV);
    const uint32_t kb = qb + 8192;
    const uint32_t vb = qb + 16384;

    // 128B rows, XOR-8 swizzle: row r (0..63), chunk g (0..7 of 16B)
    auto off8 = [](int r, int g) -> uint32_t {
        return (uint32_t)(r * 128 + ((g ^ (r & 7)) << 4));
    };

    // ---- load Q,K,V: 1536 16B chunks / 256 threads = 6 iters, coalesced ----
    const __half* base = g_QKV + (size_t)(b_ * 64) * (3 * DIMC) + hp * 64;
#pragma unroll
    for (int i = 0; i < 6; i++) {
        int idx = i * 256 + tid;          // 0..1535
        int tz  = idx >> 9;               // 0=Q,1=K,2=V
        int rem = idx & 511;
        int r = rem >> 3, g = rem & 7;
        const __half* src = base + (size_t)r * (3 * DIMC) + tz * DIMC + g * 8;
        *(uint4*)((char*)sQKV + tz * 8192 + off8(r, g)) = *(const uint4*)src;
    }
    if (tid < 8) {
        int widx = b_ & 63;
        int gh = ((widx >> 3) << 3) + tid;
        int gw = ((widx & 7) << 3) + tid;
        slabh[tid] = (gh < 56 ? 0 : (gh < 60 ? 1 : 2)) * 3;
        slabw[tid] = (gw < 56 ? 0 : (gw < 60 ? 1 : 2));
    }
    for (int i = tid; i < 450; i += 256) {
        int hh = i >= 225;
        srpb[i] = g_RPBt[(hp * 2 + hh) * 225 + (i - hh * 225)];
    }
    __syncthreads();

    // ---- S = Q @ K^T (per head): warp computes 16 q-rows x 64 keys ----
    float s[8][4];
#pragma unroll
    for (int i = 0; i < 8; i++)
#pragma unroll
        for (int j = 0; j < 4; j++) s[i][j] = 0.f;

    const int hc     = hl * 4;                 // chunk base for this head
    const int a_row  = wq * 16 + (lane & 15);
    const int a_chk0 = lane >> 4;
    const int b_row  = (lane & 7) + ((lane >> 4) << 3);
    const int b_chk0 = (lane >> 3) & 1;

#pragma unroll
    for (int ks = 0; ks < 2; ++ks) {
        uint32_t a[4], b[4][4];
        LDSM_X4(a[0], a[1], a[2], a[3], qb + off8(a_row, hc + ks * 2 + a_chk0));
#pragma unroll
        for (int nt2 = 0; nt2 < 4; ++nt2)
            LDSM_X4(b[nt2][0], b[nt2][1], b[nt2][2], b[nt2][3],
                    kb + off8(nt2 * 16 + b_row, hc + ks * 2 + b_chk0));
#pragma unroll
        for (int nt = 0; nt < 8; ++nt)
            MMA16816(s[nt], a, b[nt >> 1][(nt & 1) * 2], b[nt >> 1][(nt & 1) * 2 + 1]);
    }

    // ---- bias + mask + exp; row sums (factored zones, affine bias idx) ----
    const float scale = 0.17677669529663687f;
    const int r0 = wq * 16 + grp;
    const int r1 = r0 + 8;
    const int rh0 = r0 >> 3, rw0 = r0 & 7;
    const int rh1 = r1 >> 3;
    const int lab0 = slabh[rh0] + slabw[rw0];
    const int lab1 = slabh[rh1] + slabw[rw0];
    const int cw0  = slabw[tig * 2];
    const int cw1  = slabw[tig * 2 + 1];
    int chz[8];
#pragma unroll
    for (int i = 0; i < 8; i++) chz[i] = slabh[i];

    const float* rp = srpb + hl * 225;
    const float* p0base = rp + (rh0 + 7) * 15 + (rw0 + 7 - tig * 2);
    const float* p1base = rp + (rh1 + 7) * 15 + (rw0 + 7 - tig * 2);

    float sum0 = 0.f, sum1 = 0.f;
#pragma unroll
    for (int nt = 0; nt < 8; ++nt) {
        int lb0 = chz[nt] + cw0;
        int lb1 = chz[nt] + cw1;
        float m00 = (lab0 == lb0) ? 0.f : -100.f;
        float m01 = (lab0 == lb1) ? 0.f : -100.f;
        float m10 = (lab1 == lb0) ? 0.f : -100.f;
        float m11 = (lab1 == lb1) ? 0.f : -100.f;
        const float* p0 = p0base - nt * 15;
        const float* p1 = p1base - nt * 15;
        float e00 = __expf(s[nt][0] * scale + p0[0]  + m00);
        float e01 = __expf(s[nt][1] * scale + p0[-1] + m01);
        float e10 = __expf(s[nt][2] * scale + p1[0]  + m10);
        float e11 = __expf(s[nt][3] * scale + p1[-1] + m11);
        s[nt][0] = e00; s[nt][1] = e01;
        s[nt][2] = e10; s[nt][3] = e11;
        sum0 += e00 + e01;
        sum1 += e10 + e11;
    }
    sum0 += __shfl_xor_sync(0xffffffffu, sum0, 1);
    sum0 += __shfl_xor_sync(0xffffffffu, sum0, 2);
    sum1 += __shfl_xor_sync(0xffffffffu, sum1, 1);
    sum1 += __shfl_xor_sync(0xffffffffu, sum1, 2);

    // ---- O = P @ V (per head) ----
    float o[4][4];
#pragma unroll
    for (int i = 0; i < 4; i++)
#pragma unroll
        for (int j = 0; j < 4; j++) o[i][j] = 0.f;

#pragma unroll
    for (int ks2 = 0; ks2 < 4; ++ks2) {
        uint32_t pa[4];
        pa[0] = h2bits(s[ks2 * 2][0],     s[ks2 * 2][1]);
        pa[1] = h2bits(s[ks2 * 2][2],     s[ks2 * 2][3]);
        pa[2] = h2bits(s[ks2 * 2 + 1][0], s[ks2 * 2 + 1][1]);
        pa[3] = h2bits(s[ks2 * 2 + 1][2], s[ks2 * 2 + 1][3]);
        int vrow = ks2 * 16 + (lane & 15);
        uint32_t bv0[4], bv1[4];
        LDSM_X4_T(bv0[0], bv0[1], bv0[2], bv0[3], vb + off8(vrow, hc + (lane >> 4)));
        LDSM_X4_T(bv1[0], bv1[1], bv1[2], bv1[3], vb + off8(vrow, hc + 2 + (lane >> 4)));
        MMA16816(o[0], pa, bv0[0], bv0[1]);
        MMA16816(o[1], pa, bv0[2], bv0[3]);
        MMA16816(o[2], pa, bv1[0], bv1[1]);
        MMA16816(o[3], pa, bv1[2], bv1[3]);
    }

    // ---- stage O (both heads) in smem, then coalesced 128B row stores ----
    const float inv0 = 1.f / sum0;
    const float inv1 = 1.f / sum1;
#pragma unroll
    for (int nt = 0; nt < 4; ++nt) {
        int d = hl * 32 + nt * 8 + tig * 2;
        *(__half2*)(sO + r0 * 72 + d) = __floats2half2_rn(o[nt][0] * inv0, o[nt][1] * inv0);
        *(__half2*)(sO + r1 * 72 + d) = __floats2half2_rn(o[nt][2] * inv1, o[nt][3] * inv1);
    }
    __syncthreads();
    __half* obase = g_O + (size_t)(b_ * 64) * DIMC + hp * 64;
#pragma unroll
    for (int i = 0; i < 2; i++) {
        int idx = i * 256 + tid;            // 512 chunks of 16B
        int r = idx >> 3, ch = idx & 7;
        uint4 v = *(const uint4*)(sO + r * 72 + ch * 8);
        *(uint4*)(obase + (size_t)r * DIMC + ch * 8) = v;
    }
}

// ---------------- host launcher ----------------
extern "C" void kernel_launch(void* const* d_in, const int* in_sizes, int n_in,
                              void* d_out, int out_size) {
    const float* x      = (const float*)d_in[0];
    const float* n1g    = (const float*)d_in[1];
    const float* n1b    = (const float*)d_in[2];
    const float* qkv_w  = (const float*)d_in[3];
    const float* qkv_b  = (const float*)d_in[4];
    const float* proj_w = (const float*)d_in[5];
    const float* proj_b = (const float*)d_in[6];
    const float* rpb    = (const float*)d_in[7];
    const float* n2g    = (const float*)d_in[8];
    const float* n2b    = (const float*)d_in[9];
    const float* fc1_w  = (const float*)d_in[10];
    const float* fc1_b  = (const float*)d_in[11];
    const float* fc2_w  = (const float*)d_in[12];
    const float* fc2_b  = (const float*)d_in[13];
    float* out = (float*)d_out;

    constexpr int SMEMB = 3 * (128 * 64 * 2 + 128 * 64 * 2);  // 98304 bytes

    cudaFuncSetAttribute(gemm_f16<1536, 512, 0>, cudaFuncAttributeMaxDynamicSharedMemorySize, SMEMB);
    cudaFuncSetAttribute(gemm_f16<512,  512, 1>, cudaFuncAttributeMaxDynamicSharedMemorySize, SMEMB);
    cudaFuncSetAttribute(gemm_f16<2048, 512, 2>, cudaFuncAttributeMaxDynamicSharedMemorySize, SMEMB);
    cudaFuncSetAttribute(gemm_f16<512, 2048, 3>, cudaFuncAttributeMaxDynamicSharedMemorySize, SMEMB);

    // LN1 + shift + window partition -> g_XN1; weight cvt + rpb transpose folded in
    ln1_kernel<<<MROWS / 8, 256>>>(x, n1g, n1b, qkv_w, proj_w, fc1_w, fc2_w, rpb);

    // QKV projection
    gemm_f16<1536, 512, 0><<<dim3(1536 / 128, MROWS / 128), 256, SMEMB>>>(qkv_b, nullptr, nullptr);

    // windowed attention (tensor-core, 2 heads per block)
    attn_kernel<<<BWIN * 8, 256>>>();

    // output projection + window reverse + shift + residual -> g_XN1 (x1, fp16)
    gemm_f16<512, 512, 1><<<dim3(512 / 128, MROWS / 128), 256, SMEMB>>>(proj_b, x, nullptr);

    // LN2 (reads fp16 x1)
    ln2_kernel<<<MROWS / 8, 256>>>(n2g, n2b);

    // FC1 + gelu (fast tanh-form)
    gemm_f16<2048, 512, 2><<<dim3(2048 / 128, MROWS / 128), 256, SMEMB>>>(fc1_b, nullptr, nullptr);

    // FC2 + residual: out = x1 + acc + bias (write-only fp32)
    gemm_f16<512, 2048, 3><<<dim3(512 / 128, MROWS / 128), 256, SMEMB>>>(fc2_b, nullptr, out);
}